// round 2
// baseline (speedup 1.0000x reference)
#include <cuda_runtime.h>
#include <math.h>

#define Bn 16
#define Nn 1000
#define En 16000
#define NT 16000          /* Bn*Nn total nodes  */
#define EBASE 256000      /* Bn*En edges before self loops */
#define ETOT 272000       /* + NT self loops */
#define TWOE 32000
#define HALFB 8

#define H1n 8
#define F1 1024           /* H1*C1 */
#define EMBn 64
#define HIDn 128

// ------------------------- scratch (static, no allocs) -------------------------
__device__ __align__(16) float4 g_xf[NT];           // node features (x,y,nf,0)
__device__ __align__(16) float  g_a1s[NT * 8];
__device__ __align__(16) float  g_a1d[NT * 8];
__device__ float g_psrc[24];                         // [3][8]
__device__ float g_pdst[24];
__device__ int   g_deg[NT];
__device__ int   g_rowptr[NT + 1];
__device__ int   g_cursor[NT];
__device__ int   g_csr_src[ETOT];
__device__ float g_s[NT * 24];                       // [NT][8][3]
__device__ __align__(16) float g_x1[NT * F1];        // 65.5 MB
__device__ __align__(16) float g_h2[NT * EMBn];
__device__ float g_a2s[NT];
__device__ float g_a2d[NT];
__device__ __align__(16) float g_x2[NT * EMBn];
#define NCHUNK 128
#define CKs 500
__device__ float g_part[NCHUNK * 16 * HIDn];
__device__ float g_y1[16 * HIDn];
__device__ float g_y2[16 * HIDn];

// ------------------------- helpers -------------------------
__device__ __forceinline__ void edge_sd(int e, const int* __restrict__ EI, int& src, int& dst) {
    if (e < EBASE) {
        int b   = e / TWOE;          // graph providing src (0..7)
        int rem = e - b * TWOE;      // r*E + j
        src = EI[b * TWOE + rem] + b * Nn;
        int b2 = b + HALFB;          // graph providing dst (8..15)
        dst = EI[b2 * TWOE + rem] + b2 * Nn;
    } else {
        src = dst = e - EBASE;       // self loop
    }
}

__device__ __forceinline__ float warp_max(float v) {
    #pragma unroll
    for (int o = 16; o > 0; o >>= 1) v = fmaxf(v, __shfl_xor_sync(0xffffffffu, v, o));
    return v;
}
__device__ __forceinline__ float warp_sum(float v) {
    #pragma unroll
    for (int o = 16; o > 0; o >>= 1) v += __shfl_xor_sync(0xffffffffu, v, o);
    return v;
}
__device__ __forceinline__ float leaky(float v) { return v > 0.f ? v : 0.2f * v; }
__device__ __forceinline__ float elu(float v)   { return v > 0.f ? v : expm1f(v); }

// ------------------------- kernels -------------------------
__global__ void zero_kernel() {
    int i = blockIdx.x * blockDim.x + threadIdx.x;
    if (i < NT) g_deg[i] = 0;
}

// p_src[k][h] = sum_c W1[k, h*128+c] * att_src1[h,c]   (and p_dst)
__global__ void prep_kernel(const float* __restrict__ W1,
                            const float* __restrict__ as1,
                            const float* __restrict__ ad1) {
    int t = threadIdx.x;
    if (t >= 48) return;
    int which = t / 24;
    int r = t % 24;
    int k = r / 8, h = r % 8;
    const float* att = which ? ad1 : as1;
    float s = 0.f;
    for (int c = 0; c < 128; c++)
        s += W1[k * F1 + h * 128 + c] * att[h * 128 + c];
    (which ? g_pdst : g_psrc)[k * 8 + h] = s;
}

__global__ void node_kernel(const float* __restrict__ actions,
                            const float* __restrict__ nodef) {
    int n = blockIdx.x * blockDim.x + threadIdx.x;
    if (n >= NT) return;
    float ax = actions[n * 2 + 0];
    float ay = actions[n * 2 + 1];
    float nf = nodef[n];                 // [B,1,N] flat == n
    g_xf[n] = make_float4(ax, ay, nf, 0.f);
    #pragma unroll
    for (int h = 0; h < 8; h++) {
        g_a1s[n * 8 + h] = ax * g_psrc[h] + ay * g_psrc[8 + h] + nf * g_psrc[16 + h];
        g_a1d[n * 8 + h] = ax * g_pdst[h] + ay * g_pdst[8 + h] + nf * g_pdst[16 + h];
    }
}

__global__ void degree_kernel(const int* __restrict__ EI) {
    int e = blockIdx.x * blockDim.x + threadIdx.x;
    if (e >= ETOT) return;
    int src, dst;
    edge_sd(e, EI, src, dst);
    atomicAdd(&g_deg[dst], 1);
}

__global__ void scan_kernel() {
    __shared__ int sdata[1024];
    int t = threadIdx.x;
    int base = t * 16;
    int vals[16];
    int local = 0;
    #pragma unroll
    for (int i = 0; i < 16; i++) {
        int idx = base + i;
        int v = (idx < NT) ? g_deg[idx] : 0;
        vals[i] = local;
        local += v;
    }
    sdata[t] = local;
    __syncthreads();
    for (int off = 1; off < 1024; off <<= 1) {
        int v = (t >= off) ? sdata[t - off] : 0;
        __syncthreads();
        sdata[t] += v;
        __syncthreads();
    }
    int excl = (t == 0) ? 0 : sdata[t - 1];
    #pragma unroll
    for (int i = 0; i < 16; i++) {
        int idx = base + i;
        if (idx < NT) {
            int rp = excl + vals[i];
            g_rowptr[idx] = rp;
            g_cursor[idx] = rp;
        }
    }
    if (t == 1023) g_rowptr[NT] = sdata[1023];
}

__global__ void scatter_kernel(const int* __restrict__ EI) {
    int e = blockIdx.x * blockDim.x + threadIdx.x;
    if (e >= ETOT) return;
    int src, dst;
    edge_sd(e, EI, src, dst);
    int pos = atomicAdd(&g_cursor[dst], 1);
    g_csr_src[pos] = src;
}

// per-dst softmax + 3-vector accumulation  s[d][h][k] = sum_e w_e * x[src_e][k]
__global__ void conv1_attn_kernel() {
    int wg = (blockIdx.x * blockDim.x + threadIdx.x) >> 5;
    if (wg >= NT) return;
    int lane = threadIdx.x & 31;
    int d = wg;
    int start = g_rowptr[d];
    int deg = g_rowptr[d + 1] - start;
    float4 t0 = *(const float4*)&g_a1d[d * 8];
    float4 t1 = *(const float4*)&g_a1d[d * 8 + 4];
    float ad[8] = { t0.x, t0.y, t0.z, t0.w, t1.x, t1.y, t1.z, t1.w };
    #pragma unroll
    for (int h = 0; h < 8; h++) {
        float m = -1e30f;
        for (int e = lane; e < deg; e += 32) {
            int s = g_csr_src[start + e];
            float v = leaky(g_a1s[s * 8 + h] + ad[h]);
            m = fmaxf(m, v);
        }
        m = warp_max(m);
        float se = 0.f, s0 = 0.f, s1 = 0.f, s2 = 0.f;
        for (int e = lane; e < deg; e += 32) {
            int s = g_csr_src[start + e];
            float v = leaky(g_a1s[s * 8 + h] + ad[h]);
            float ea = __expf(v - m);
            se += ea;
            float4 x = g_xf[s];
            s0 += ea * x.x; s1 += ea * x.y; s2 += ea * x.z;
        }
        se = warp_sum(se); s0 = warp_sum(s0); s1 = warp_sum(s1); s2 = warp_sum(s2);
        if (lane == 0) {
            float inv = 1.0f / se;
            g_s[d * 24 + h * 3 + 0] = s0 * inv;
            g_s[d * 24 + h * 3 + 1] = s1 * inv;
            g_s[d * 24 + h * 3 + 2] = s2 * inv;
        }
    }
}

// x1[n][col] = elu( sum_k s[n][h][k]*W1[k][col] + b1[col] )     (vectorized x4)
__global__ void expand_kernel(const float* __restrict__ W1, const float* __restrict__ b1) {
    int idx = blockIdx.x * blockDim.x + threadIdx.x;   // one per float4
    int n = idx >> 8;
    int c4 = (idx & 255) * 4;
    int h = c4 >> 7;
    float s0 = g_s[n * 24 + h * 3 + 0];
    float s1 = g_s[n * 24 + h * 3 + 1];
    float s2 = g_s[n * 24 + h * 3 + 2];
    float4 w0 = *(const float4*)&W1[c4];
    float4 w1 = *(const float4*)&W1[F1 + c4];
    float4 w2 = *(const float4*)&W1[2 * F1 + c4];
    float4 bb = *(const float4*)&b1[c4];
    float4 r;
    r.x = elu(s0 * w0.x + s1 * w1.x + s2 * w2.x + bb.x);
    r.y = elu(s0 * w0.y + s1 * w1.y + s2 * w2.y + bb.y);
    r.z = elu(s0 * w0.z + s1 * w1.z + s2 * w2.z + bb.z);
    r.w = elu(s0 * w0.w + s1 * w1.w + s2 * w2.w + bb.w);
    *(float4*)&g_x1[n * F1 + c4] = r;
}

// h2 = x1[16000,1024] @ W2[1024,64]
__global__ __launch_bounds__(256) void gemm2_kernel(const float* __restrict__ Bw) {
    __shared__ float As[64][33];
    __shared__ float Bs[32][64];
    int tid = threadIdx.x;
    int row0 = blockIdx.x * 64;
    int tx = tid % 16, ty = tid / 16;
    int la_row = tid / 8;
    int la_c4 = (tid % 8) * 4;
    int lb_k = tid / 16;
    int lb_c4 = (tid % 16) * 4;
    float acc[4][4];
    #pragma unroll
    for (int i = 0; i < 4; i++)
        #pragma unroll
        for (int j = 0; j < 4; j++) acc[i][j] = 0.f;

    for (int kc = 0; kc < F1; kc += 32) {
        #pragma unroll
        for (int rr = 0; rr < 2; rr++) {
            int r = la_row + rr * 32;
            float4 v = *(const float4*)&g_x1[(row0 + r) * F1 + kc + la_c4];
            As[r][la_c4 + 0] = v.x; As[r][la_c4 + 1] = v.y;
            As[r][la_c4 + 2] = v.z; As[r][la_c4 + 3] = v.w;
        }
        #pragma unroll
        for (int rr = 0; rr < 2; rr++) {
            int k = lb_k + rr * 16;
            *(float4*)&Bs[k][lb_c4] = *(const float4*)&Bw[(kc + k) * EMBn + lb_c4];
        }
        __syncthreads();
        #pragma unroll
        for (int kk = 0; kk < 32; kk++) {
            float a0 = As[ty * 4 + 0][kk];
            float a1 = As[ty * 4 + 1][kk];
            float a2 = As[ty * 4 + 2][kk];
            float a3 = As[ty * 4 + 3][kk];
            float4 b = *(const float4*)&Bs[kk][tx * 4];
            acc[0][0] += a0 * b.x; acc[0][1] += a0 * b.y; acc[0][2] += a0 * b.z; acc[0][3] += a0 * b.w;
            acc[1][0] += a1 * b.x; acc[1][1] += a1 * b.y; acc[1][2] += a1 * b.z; acc[1][3] += a1 * b.w;
            acc[2][0] += a2 * b.x; acc[2][1] += a2 * b.y; acc[2][2] += a2 * b.z; acc[2][3] += a2 * b.w;
            acc[3][0] += a3 * b.x; acc[3][1] += a3 * b.y; acc[3][2] += a3 * b.z; acc[3][3] += a3 * b.w;
        }
        __syncthreads();
    }
    #pragma unroll
    for (int i = 0; i < 4; i++)
        #pragma unroll
        for (int j = 0; j < 4; j++)
            g_h2[(row0 + ty * 4 + i) * EMBn + tx * 4 + j] = acc[i][j];
}

// a2s[n] = h2[n] . att_src2 ; a2d[n] = h2[n] . att_dst2   (warp per node)
__global__ void attn2_kernel(const float* __restrict__ as2, const float* __restrict__ ad2) {
    int wg = (blockIdx.x * blockDim.x + threadIdx.x) >> 5;
    if (wg >= NT) return;
    int lane = threadIdx.x & 31;
    float v0 = g_h2[wg * 64 + lane];
    float v1 = g_h2[wg * 64 + 32 + lane];
    float ss = v0 * as2[lane] + v1 * as2[32 + lane];
    float sd = v0 * ad2[lane] + v1 * ad2[32 + lane];
    ss = warp_sum(ss);
    sd = warp_sum(sd);
    if (lane == 0) { g_a2s[wg] = ss; g_a2d[wg] = sd; }
}

// per-dst softmax + aggregation of h2, fused elu(+b2) -> x2
__global__ void conv2_agg_kernel(const float* __restrict__ b2) {
    __shared__ float wbuf[8][128];
    __shared__ int   ibuf[8][128];
    int wg = (blockIdx.x * blockDim.x + threadIdx.x) >> 5;
    if (wg >= NT) return;
    int lane = threadIdx.x & 31;
    int w = (threadIdx.x >> 5) & 7;
    int d = wg;
    int start = g_rowptr[d];
    int deg = g_rowptr[d + 1] - start;
    float adv = g_a2d[d];
    float m = -1e30f;
    for (int e = lane; e < deg; e += 32) {
        int s = g_csr_src[start + e];
        m = fmaxf(m, leaky(g_a2s[s] + adv));
    }
    m = warp_max(m);
    float se = 0.f, acc0 = 0.f, acc1 = 0.f;
    for (int base = 0; base < deg; base += 128) {
        int cnt = min(128, deg - base);
        for (int e = lane; e < cnt; e += 32) {
            int s = g_csr_src[start + base + e];
            float ea = __expf(leaky(g_a2s[s] + adv) - m);
            wbuf[w][e] = ea;
            ibuf[w][e] = s;
            se += ea;
        }
        __syncwarp();
        #pragma unroll 4
        for (int e = 0; e < cnt; e++) {
            float ea = wbuf[w][e];
            int s = ibuf[w][e];
            acc0 += ea * g_h2[s * 64 + lane];
            acc1 += ea * g_h2[s * 64 + 32 + lane];
        }
        __syncwarp();
    }
    se = warp_sum(se);
    float inv = 1.0f / se;
    float r0 = acc0 * inv + b2[lane];
    float r1 = acc1 * inv + b2[32 + lane];
    g_x2[d * 64 + lane]      = elu(r0);
    g_x2[d * 64 + 32 + lane] = elu(r1);
}

// split-K stage 1: partial[c][b][j] = sum_{k in chunk} x2flat[b][k] * mw1[k][j]
__global__ void mlp1_stage1(const float* __restrict__ mw1) {
    int c = blockIdx.x;
    int j = threadIdx.x & 127;
    int bh = threadIdx.x >> 7;       // 0/1 -> b halves
    int k0 = c * CKs;
    float acc[8] = {0, 0, 0, 0, 0, 0, 0, 0};
    const float* xb = g_x2 + bh * 8 * 64000 + k0;   // flat [16][64000]
    for (int k = 0; k < CKs; k++) {
        float wv = mw1[(k0 + k) * HIDn + j];
        #pragma unroll
        for (int b = 0; b < 8; b++)
            acc[b] += xb[b * 64000 + k] * wv;
    }
    #pragma unroll
    for (int b = 0; b < 8; b++)
        g_part[(c * 16 + bh * 8 + b) * HIDn + j] = acc[b];
}

__global__ void mlp1_reduce(const float* __restrict__ mb1) {
    int idx = blockIdx.x * blockDim.x + threadIdx.x;
    if (idx >= 16 * HIDn) return;
    int b = idx >> 7, j = idx & 127;
    float s = 0.f;
    for (int c = 0; c < NCHUNK; c++)
        s += g_part[(c * 16 + b) * HIDn + j];
    s += mb1[j];
    g_y1[b * HIDn + j] = fmaxf(s, 0.f);
}

__global__ void mlp2_kernel(const float* __restrict__ mw2, const float* __restrict__ mb2) {
    __shared__ float ys[16 * HIDn];
    int tid = threadIdx.x;
    for (int i = tid; i < 16 * HIDn; i += 128) ys[i] = g_y1[i];
    __syncthreads();
    int j = tid;
    float acc[16];
    #pragma unroll
    for (int b = 0; b < 16; b++) acc[b] = 0.f;
    for (int k = 0; k < HIDn; k++) {
        float wv = mw2[k * HIDn + j];
        #pragma unroll
        for (int b = 0; b < 16; b++)
            acc[b] += ys[b * HIDn + k] * wv;
    }
    #pragma unroll
    for (int b = 0; b < 16; b++)
        g_y2[b * HIDn + j] = fmaxf(acc[b] + mb2[j], 0.f);
}

__global__ void out_kernel(const float* __restrict__ ow, const float* __restrict__ ob,
                           float* __restrict__ out) {
    __shared__ float ys[16 * HIDn];
    int tid = threadIdx.x;
    for (int i = tid; i < 16 * HIDn; i += 128) ys[i] = g_y2[i];
    __syncthreads();
    int j = blockIdx.x * 128 + tid;
    if (j >= Nn) return;
    float acc[16];
    #pragma unroll
    for (int b = 0; b < 16; b++) acc[b] = 0.f;
    for (int k = 0; k < HIDn; k++) {
        float wv = ow[k * Nn + j];
        #pragma unroll
        for (int b = 0; b < 16; b++)
            acc[b] += ys[b * HIDn + k] * wv;
    }
    #pragma unroll
    for (int b = 0; b < 16; b++) {
        float v = acc[b] + ob[j];
        out[b * Nn + j] = 1.0f / (1.0f + __expf(-v));
    }
}

// ------------------------- launch -------------------------
extern "C" void kernel_launch(void* const* d_in, const int* in_sizes, int n_in,
                              void* d_out, int out_size) {
    const float* actions = (const float*)d_in[0];
    const float* nodef   = (const float*)d_in[1];
    const int*   ei      = (const int*)d_in[2];
    const float* W1  = (const float*)d_in[3];
    const float* as1 = (const float*)d_in[4];
    const float* ad1 = (const float*)d_in[5];
    const float* b1  = (const float*)d_in[6];
    const float* W2  = (const float*)d_in[7];
    const float* as2 = (const float*)d_in[8];
    const float* ad2 = (const float*)d_in[9];
    const float* b2  = (const float*)d_in[10];
    const float* mw1 = (const float*)d_in[11];
    const float* mb1 = (const float*)d_in[12];
    const float* mw2 = (const float*)d_in[13];
    const float* mb2 = (const float*)d_in[14];
    const float* ow  = (const float*)d_in[15];
    const float* ob  = (const float*)d_in[16];
    float* out = (float*)d_out;

    zero_kernel<<<(NT + 255) / 256, 256>>>();
    prep_kernel<<<1, 64>>>(W1, as1, ad1);
    node_kernel<<<(NT + 255) / 256, 256>>>(actions, nodef);
    degree_kernel<<<(ETOT + 255) / 256, 256>>>(ei);
    scan_kernel<<<1, 1024>>>();
    scatter_kernel<<<(ETOT + 255) / 256, 256>>>(ei);
    conv1_attn_kernel<<<NT / 8, 256>>>();
    expand_kernel<<<NT, 256>>>(W1, b1);              // 16000 blocks, 1 float4/thread
    gemm2_kernel<<<NT / 64, 256>>>(W2);
    attn2_kernel<<<NT / 8, 256>>>(as2, ad2);
    conv2_agg_kernel<<<NT / 8, 256>>>(b2);
    mlp1_stage1<<<NCHUNK, 256>>>(mw1);
    mlp1_reduce<<<8, 256>>>(mb1);
    mlp2_kernel<<<1, 128>>>(mw2, mb2);
    out_kernel<<<8, 128>>>(ow, ob, out);
}

// round 3
// speedup vs baseline: 1.0022x; 1.0022x over previous
#include <cuda_runtime.h>
#include <math.h>

#define Bn 16
#define Nn 1000
#define En 16000
#define NT 16000          /* Bn*Nn total nodes  */
#define EBASE 256000      /* Bn*En edges before self loops */
#define ETOT 272000       /* + NT self loops */
#define TWOE 32000
#define HALFB 8

#define H1n 8
#define F1 1024           /* H1*C1 */
#define EMBn 64
#define HIDn 128

// ------------------------- scratch (static, no allocs) -------------------------
__device__ __align__(16) float4 g_xf[NT];           // node features (x,y,nf,0)
__device__ __align__(16) float  g_a1s[NT * 8];
__device__ __align__(16) float  g_a1d[NT * 8];
__device__ float g_psrc[24];                         // [3][8]
__device__ float g_pdst[24];
__device__ int   g_deg[NT];
__device__ int   g_rowptr[NT + 1];
__device__ int   g_cursor[NT];
__device__ int   g_csr_src[ETOT];
__device__ float g_s[NT * 24];                       // [NT][8][3]
__device__ __align__(16) float g_x1[NT * F1];        // 65.5 MB
__device__ __align__(16) float g_h2[NT * EMBn];
__device__ float g_a2s[NT];
__device__ float g_a2d[NT];
__device__ __align__(16) float g_x2[NT * EMBn];
#define NCHUNK 128
#define CKs 500
__device__ float g_part[NCHUNK * 16 * HIDn];
__device__ float g_y1[16 * HIDn];
__device__ float g_y2[16 * HIDn];

// ------------------------- helpers -------------------------
__device__ __forceinline__ void edge_sd(int e, const int* __restrict__ EI, int& src, int& dst) {
    if (e < EBASE) {
        int b   = e / TWOE;          // graph providing src (0..7)
        int rem = e - b * TWOE;      // r*E + j
        src = EI[b * TWOE + rem] + b * Nn;
        int b2 = b + HALFB;          // graph providing dst (8..15)
        dst = EI[b2 * TWOE + rem] + b2 * Nn;
    } else {
        src = dst = e - EBASE;       // self loop
    }
}

__device__ __forceinline__ float warp_max(float v) {
    #pragma unroll
    for (int o = 16; o > 0; o >>= 1) v = fmaxf(v, __shfl_xor_sync(0xffffffffu, v, o));
    return v;
}
__device__ __forceinline__ float warp_sum(float v) {
    #pragma unroll
    for (int o = 16; o > 0; o >>= 1) v += __shfl_xor_sync(0xffffffffu, v, o);
    return v;
}
__device__ __forceinline__ float leaky(float v) { return v > 0.f ? v : 0.2f * v; }
__device__ __forceinline__ float elu(float v)   { return v > 0.f ? v : expm1f(v); }

// ------------------------- kernels -------------------------
__global__ void zero_kernel() {
    int i = blockIdx.x * blockDim.x + threadIdx.x;
    if (i < NT) g_deg[i] = 0;
}

// p_src[k][h] = sum_c W1[k, h*128+c] * att_src1[h,c]   (and p_dst)
__global__ void prep_kernel(const float* __restrict__ W1,
                            const float* __restrict__ as1,
                            const float* __restrict__ ad1) {
    int t = threadIdx.x;
    if (t >= 48) return;
    int which = t / 24;
    int r = t % 24;
    int k = r / 8, h = r % 8;
    const float* att = which ? ad1 : as1;
    float s = 0.f;
    for (int c = 0; c < 128; c++)
        s += W1[k * F1 + h * 128 + c] * att[h * 128 + c];
    (which ? g_pdst : g_psrc)[k * 8 + h] = s;
}

__global__ void node_kernel(const float* __restrict__ actions,
                            const float* __restrict__ nodef) {
    int n = blockIdx.x * blockDim.x + threadIdx.x;
    if (n >= NT) return;
    float ax = actions[n * 2 + 0];
    float ay = actions[n * 2 + 1];
    float nf = nodef[n];                 // [B,1,N] flat == n
    g_xf[n] = make_float4(ax, ay, nf, 0.f);
    #pragma unroll
    for (int h = 0; h < 8; h++) {
        g_a1s[n * 8 + h] = ax * g_psrc[h] + ay * g_psrc[8 + h] + nf * g_psrc[16 + h];
        g_a1d[n * 8 + h] = ax * g_pdst[h] + ay * g_pdst[8 + h] + nf * g_pdst[16 + h];
    }
}

__global__ void degree_kernel(const int* __restrict__ EI) {
    int e = blockIdx.x * blockDim.x + threadIdx.x;
    if (e >= ETOT) return;
    int src, dst;
    edge_sd(e, EI, src, dst);
    atomicAdd(&g_deg[dst], 1);
}

__global__ void scan_kernel() {
    __shared__ int sdata[1024];
    int t = threadIdx.x;
    int base = t * 16;
    int vals[16];
    int local = 0;
    #pragma unroll
    for (int i = 0; i < 16; i++) {
        int idx = base + i;
        int v = (idx < NT) ? g_deg[idx] : 0;
        vals[i] = local;
        local += v;
    }
    sdata[t] = local;
    __syncthreads();
    for (int off = 1; off < 1024; off <<= 1) {
        int v = (t >= off) ? sdata[t - off] : 0;
        __syncthreads();
        sdata[t] += v;
        __syncthreads();
    }
    int excl = (t == 0) ? 0 : sdata[t - 1];
    #pragma unroll
    for (int i = 0; i < 16; i++) {
        int idx = base + i;
        if (idx < NT) {
            int rp = excl + vals[i];
            g_rowptr[idx] = rp;
            g_cursor[idx] = rp;
        }
    }
    if (t == 1023) g_rowptr[NT] = sdata[1023];
}

__global__ void scatter_kernel(const int* __restrict__ EI) {
    int e = blockIdx.x * blockDim.x + threadIdx.x;
    if (e >= ETOT) return;
    int src, dst;
    edge_sd(e, EI, src, dst);
    int pos = atomicAdd(&g_cursor[dst], 1);
    g_csr_src[pos] = src;
}

// per-dst softmax + 3-vector accumulation  s[d][h][k] = sum_e w_e * x[src_e][k]
__global__ void conv1_attn_kernel() {
    int wg = (blockIdx.x * blockDim.x + threadIdx.x) >> 5;
    if (wg >= NT) return;
    int lane = threadIdx.x & 31;
    int d = wg;
    int start = g_rowptr[d];
    int deg = g_rowptr[d + 1] - start;
    float4 t0 = *(const float4*)&g_a1d[d * 8];
    float4 t1 = *(const float4*)&g_a1d[d * 8 + 4];
    float ad[8] = { t0.x, t0.y, t0.z, t0.w, t1.x, t1.y, t1.z, t1.w };
    #pragma unroll
    for (int h = 0; h < 8; h++) {
        float m = -1e30f;
        for (int e = lane; e < deg; e += 32) {
            int s = g_csr_src[start + e];
            float v = leaky(g_a1s[s * 8 + h] + ad[h]);
            m = fmaxf(m, v);
        }
        m = warp_max(m);
        float se = 0.f, s0 = 0.f, s1 = 0.f, s2 = 0.f;
        for (int e = lane; e < deg; e += 32) {
            int s = g_csr_src[start + e];
            float v = leaky(g_a1s[s * 8 + h] + ad[h]);
            float ea = __expf(v - m);
            se += ea;
            float4 x = g_xf[s];
            s0 += ea * x.x; s1 += ea * x.y; s2 += ea * x.z;
        }
        se = warp_sum(se); s0 = warp_sum(s0); s1 = warp_sum(s1); s2 = warp_sum(s2);
        if (lane == 0) {
            float inv = 1.0f / se;
            g_s[d * 24 + h * 3 + 0] = s0 * inv;
            g_s[d * 24 + h * 3 + 1] = s1 * inv;
            g_s[d * 24 + h * 3 + 2] = s2 * inv;
        }
    }
}

// x1[n][col] = elu( sum_k s[n][h][k]*W1[k][col] + b1[col] )     (vectorized x4)
__global__ void expand_kernel(const float* __restrict__ W1, const float* __restrict__ b1) {
    int idx = blockIdx.x * blockDim.x + threadIdx.x;   // one per float4
    int n = idx >> 8;
    int c4 = (idx & 255) * 4;
    int h = c4 >> 7;
    float s0 = g_s[n * 24 + h * 3 + 0];
    float s1 = g_s[n * 24 + h * 3 + 1];
    float s2 = g_s[n * 24 + h * 3 + 2];
    float4 w0 = *(const float4*)&W1[c4];
    float4 w1 = *(const float4*)&W1[F1 + c4];
    float4 w2 = *(const float4*)&W1[2 * F1 + c4];
    float4 bb = *(const float4*)&b1[c4];
    float4 r;
    r.x = elu(s0 * w0.x + s1 * w1.x + s2 * w2.x + bb.x);
    r.y = elu(s0 * w0.y + s1 * w1.y + s2 * w2.y + bb.y);
    r.z = elu(s0 * w0.z + s1 * w1.z + s2 * w2.z + bb.z);
    r.w = elu(s0 * w0.w + s1 * w1.w + s2 * w2.w + bb.w);
    *(float4*)&g_x1[n * F1 + c4] = r;
}

// h2 = x1[16000,1024] @ W2[1024,64]
__global__ __launch_bounds__(256) void gemm2_kernel(const float* __restrict__ Bw) {
    __shared__ float As[64][33];
    __shared__ float Bs[32][64];
    int tid = threadIdx.x;
    int row0 = blockIdx.x * 64;
    int tx = tid % 16, ty = tid / 16;
    int la_row = tid / 8;
    int la_c4 = (tid % 8) * 4;
    int lb_k = tid / 16;
    int lb_c4 = (tid % 16) * 4;
    float acc[4][4];
    #pragma unroll
    for (int i = 0; i < 4; i++)
        #pragma unroll
        for (int j = 0; j < 4; j++) acc[i][j] = 0.f;

    for (int kc = 0; kc < F1; kc += 32) {
        #pragma unroll
        for (int rr = 0; rr < 2; rr++) {
            int r = la_row + rr * 32;
            float4 v = *(const float4*)&g_x1[(row0 + r) * F1 + kc + la_c4];
            As[r][la_c4 + 0] = v.x; As[r][la_c4 + 1] = v.y;
            As[r][la_c4 + 2] = v.z; As[r][la_c4 + 3] = v.w;
        }
        #pragma unroll
        for (int rr = 0; rr < 2; rr++) {
            int k = lb_k + rr * 16;
            *(float4*)&Bs[k][lb_c4] = *(const float4*)&Bw[(kc + k) * EMBn + lb_c4];
        }
        __syncthreads();
        #pragma unroll
        for (int kk = 0; kk < 32; kk++) {
            float a0 = As[ty * 4 + 0][kk];
            float a1 = As[ty * 4 + 1][kk];
            float a2 = As[ty * 4 + 2][kk];
            float a3 = As[ty * 4 + 3][kk];
            float4 b = *(const float4*)&Bs[kk][tx * 4];
            acc[0][0] += a0 * b.x; acc[0][1] += a0 * b.y; acc[0][2] += a0 * b.z; acc[0][3] += a0 * b.w;
            acc[1][0] += a1 * b.x; acc[1][1] += a1 * b.y; acc[1][2] += a1 * b.z; acc[1][3] += a1 * b.w;
            acc[2][0] += a2 * b.x; acc[2][1] += a2 * b.y; acc[2][2] += a2 * b.z; acc[2][3] += a2 * b.w;
            acc[3][0] += a3 * b.x; acc[3][1] += a3 * b.y; acc[3][2] += a3 * b.z; acc[3][3] += a3 * b.w;
        }
        __syncthreads();
    }
    #pragma unroll
    for (int i = 0; i < 4; i++)
        #pragma unroll
        for (int j = 0; j < 4; j++)
            g_h2[(row0 + ty * 4 + i) * EMBn + tx * 4 + j] = acc[i][j];
}

// a2s[n] = h2[n] . att_src2 ; a2d[n] = h2[n] . att_dst2   (warp per node)
__global__ void attn2_kernel(const float* __restrict__ as2, const float* __restrict__ ad2) {
    int wg = (blockIdx.x * blockDim.x + threadIdx.x) >> 5;
    if (wg >= NT) return;
    int lane = threadIdx.x & 31;
    float v0 = g_h2[wg * 64 + lane];
    float v1 = g_h2[wg * 64 + 32 + lane];
    float ss = v0 * as2[lane] + v1 * as2[32 + lane];
    float sd = v0 * ad2[lane] + v1 * ad2[32 + lane];
    ss = warp_sum(ss);
    sd = warp_sum(sd);
    if (lane == 0) { g_a2s[wg] = ss; g_a2d[wg] = sd; }
}

// per-dst softmax + aggregation of h2, fused elu(+b2) -> x2
__global__ void conv2_agg_kernel(const float* __restrict__ b2) {
    __shared__ float wbuf[8][128];
    __shared__ int   ibuf[8][128];
    int wg = (blockIdx.x * blockDim.x + threadIdx.x) >> 5;
    if (wg >= NT) return;
    int lane = threadIdx.x & 31;
    int w = (threadIdx.x >> 5) & 7;
    int d = wg;
    int start = g_rowptr[d];
    int deg = g_rowptr[d + 1] - start;
    float adv = g_a2d[d];
    float m = -1e30f;
    for (int e = lane; e < deg; e += 32) {
        int s = g_csr_src[start + e];
        m = fmaxf(m, leaky(g_a2s[s] + adv));
    }
    m = warp_max(m);
    float se = 0.f, acc0 = 0.f, acc1 = 0.f;
    for (int base = 0; base < deg; base += 128) {
        int cnt = min(128, deg - base);
        for (int e = lane; e < cnt; e += 32) {
            int s = g_csr_src[start + base + e];
            float ea = __expf(leaky(g_a2s[s] + adv) - m);
            wbuf[w][e] = ea;
            ibuf[w][e] = s;
            se += ea;
        }
        __syncwarp();
        #pragma unroll 4
        for (int e = 0; e < cnt; e++) {
            float ea = wbuf[w][e];
            int s = ibuf[w][e];
            acc0 += ea * g_h2[s * 64 + lane];
            acc1 += ea * g_h2[s * 64 + 32 + lane];
        }
        __syncwarp();
    }
    se = warp_sum(se);
    float inv = 1.0f / se;
    float r0 = acc0 * inv + b2[lane];
    float r1 = acc1 * inv + b2[32 + lane];
    g_x2[d * 64 + lane]      = elu(r0);
    g_x2[d * 64 + 32 + lane] = elu(r1);
}

// split-K stage 1: partial[c][b][j] = sum_{k in chunk} x2flat[b][k] * mw1[k][j]
__global__ void mlp1_stage1(const float* __restrict__ mw1) {
    int c = blockIdx.x;
    int j = threadIdx.x & 127;
    int bh = threadIdx.x >> 7;       // 0/1 -> b halves
    int k0 = c * CKs;
    float acc[8] = {0, 0, 0, 0, 0, 0, 0, 0};
    const float* xb = g_x2 + bh * 8 * 64000 + k0;   // flat [16][64000]
    for (int k = 0; k < CKs; k++) {
        float wv = mw1[(k0 + k) * HIDn + j];
        #pragma unroll
        for (int b = 0; b < 8; b++)
            acc[b] += xb[b * 64000 + k] * wv;
    }
    #pragma unroll
    for (int b = 0; b < 8; b++)
        g_part[(c * 16 + bh * 8 + b) * HIDn + j] = acc[b];
}

__global__ void mlp1_reduce(const float* __restrict__ mb1) {
    int idx = blockIdx.x * blockDim.x + threadIdx.x;
    if (idx >= 16 * HIDn) return;
    int b = idx >> 7, j = idx & 127;
    float s = 0.f;
    for (int c = 0; c < NCHUNK; c++)
        s += g_part[(c * 16 + b) * HIDn + j];
    s += mb1[j];
    g_y1[b * HIDn + j] = fmaxf(s, 0.f);
}

__global__ void mlp2_kernel(const float* __restrict__ mw2, const float* __restrict__ mb2) {
    __shared__ float ys[16 * HIDn];
    int tid = threadIdx.x;
    for (int i = tid; i < 16 * HIDn; i += 128) ys[i] = g_y1[i];
    __syncthreads();
    int j = tid;
    float acc[16];
    #pragma unroll
    for (int b = 0; b < 16; b++) acc[b] = 0.f;
    for (int k = 0; k < HIDn; k++) {
        float wv = mw2[k * HIDn + j];
        #pragma unroll
        for (int b = 0; b < 16; b++)
            acc[b] += ys[b * HIDn + k] * wv;
    }
    #pragma unroll
    for (int b = 0; b < 16; b++)
        g_y2[b * HIDn + j] = fmaxf(acc[b] + mb2[j], 0.f);
}

__global__ void out_kernel(const float* __restrict__ ow, const float* __restrict__ ob,
                           float* __restrict__ out) {
    __shared__ float ys[16 * HIDn];
    int tid = threadIdx.x;
    for (int i = tid; i < 16 * HIDn; i += 128) ys[i] = g_y2[i];
    __syncthreads();
    int j = blockIdx.x * 128 + tid;
    if (j >= Nn) return;
    float acc[16];
    #pragma unroll
    for (int b = 0; b < 16; b++) acc[b] = 0.f;
    for (int k = 0; k < HIDn; k++) {
        float wv = ow[k * Nn + j];
        #pragma unroll
        for (int b = 0; b < 16; b++)
            acc[b] += ys[b * HIDn + k] * wv;
    }
    #pragma unroll
    for (int b = 0; b < 16; b++) {
        float v = acc[b] + ob[j];
        out[b * Nn + j] = 1.0f / (1.0f + __expf(-v));
    }
}

// ------------------------- launch -------------------------
extern "C" void kernel_launch(void* const* d_in, const int* in_sizes, int n_in,
                              void* d_out, int out_size) {
    const float* actions = (const float*)d_in[0];
    const float* nodef   = (const float*)d_in[1];
    const int*   ei      = (const int*)d_in[2];
    const float* W1  = (const float*)d_in[3];
    const float* as1 = (const float*)d_in[4];
    const float* ad1 = (const float*)d_in[5];
    const float* b1  = (const float*)d_in[6];
    const float* W2  = (const float*)d_in[7];
    const float* as2 = (const float*)d_in[8];
    const float* ad2 = (const float*)d_in[9];
    const float* b2  = (const float*)d_in[10];
    const float* mw1 = (const float*)d_in[11];
    const float* mb1 = (const float*)d_in[12];
    const float* mw2 = (const float*)d_in[13];
    const float* mb2 = (const float*)d_in[14];
    const float* ow  = (const float*)d_in[15];
    const float* ob  = (const float*)d_in[16];
    float* out = (float*)d_out;

    zero_kernel<<<(NT + 255) / 256, 256>>>();
    prep_kernel<<<1, 64>>>(W1, as1, ad1);
    node_kernel<<<(NT + 255) / 256, 256>>>(actions, nodef);
    degree_kernel<<<(ETOT + 255) / 256, 256>>>(ei);
    scan_kernel<<<1, 1024>>>();
    scatter_kernel<<<(ETOT + 255) / 256, 256>>>(ei);
    conv1_attn_kernel<<<NT / 8, 256>>>();
    expand_kernel<<<NT, 256>>>(W1, b1);              // 16000 blocks, 1 float4/thread
    gemm2_kernel<<<NT / 64, 256>>>(W2);
    attn2_kernel<<<NT / 8, 256>>>(as2, ad2);
    conv2_agg_kernel<<<NT / 8, 256>>>(b2);
    mlp1_stage1<<<NCHUNK, 256>>>(mw1);
    mlp1_reduce<<<8, 256>>>(mb1);
    mlp2_kernel<<<1, 128>>>(mw2, mb2);
    out_kernel<<<8, 128>>>(ow, ob, out);
}

// round 4
// speedup vs baseline: 1.4952x; 1.4919x over previous
#include <cuda_runtime.h>
#include <math.h>

#define Bn 16
#define Nn 1000
#define En 16000
#define NT 16000          /* Bn*Nn total nodes  */
#define EBASE 256000      /* Bn*En edges before self loops */
#define ETOT 272000       /* + NT self loops */
#define TWOE 32000
#define HALFB 8

#define H1n 8
#define F1 1024           /* H1*C1 */
#define EMBn 64
#define HIDn 128

// ------------------------- scratch (static, no allocs) -------------------------
__device__ __align__(16) float4 g_xf[NT];           // node features (x,y,nf,0)
__device__ float g_psrc[24];                         // [3][8]
__device__ float g_pdst[24];
__device__ int   g_deg[NT];
__device__ int   g_rowptr[NT + 1];
__device__ int   g_cursor[NT];
__device__ int   g_csr_src[ETOT];
__device__ float g_s[NT * 24];                       // [NT][8][3]
__device__ __align__(16) float g_h2[NT * EMBn];
__device__ float g_a2s[NT];
__device__ float g_a2d[NT];
__device__ __align__(16) float g_x2[NT * EMBn];
#define NCHUNK 128
#define CKs 500
__device__ float g_part[NCHUNK * 16 * HIDn];
__device__ float g_y1[16 * HIDn];
__device__ float g_y2[16 * HIDn];

// ------------------------- helpers -------------------------
__device__ __forceinline__ void edge_sd(int e, const int* __restrict__ EI, int& src, int& dst) {
    if (e < EBASE) {
        int b   = e / TWOE;          // graph providing src (0..7)
        int rem = e - b * TWOE;      // r*E + j
        src = EI[b * TWOE + rem] + b * Nn;
        int b2 = b + HALFB;          // graph providing dst (8..15)
        dst = EI[b2 * TWOE + rem] + b2 * Nn;
    } else {
        src = dst = e - EBASE;       // self loop
    }
}

__device__ __forceinline__ float warp_sum(float v) {
    #pragma unroll
    for (int o = 16; o > 0; o >>= 1) v += __shfl_xor_sync(0xffffffffu, v, o);
    return v;
}
__device__ __forceinline__ float leaky(float v) { return v > 0.f ? v : 0.2f * v; }
__device__ __forceinline__ float elu(float v)   { return v > 0.f ? v : (__expf(v) - 1.0f); }

// packed fp32x2 FMA (sm_100+): d = a*b + c on both lanes
__device__ __forceinline__ float2 ffma2(float2 a, float2 b, float2 c) {
    unsigned long long A = *reinterpret_cast<unsigned long long*>(&a);
    unsigned long long B = *reinterpret_cast<unsigned long long*>(&b);
    unsigned long long C = *reinterpret_cast<unsigned long long*>(&c);
    unsigned long long D;
    asm("fma.rn.f32x2 %0, %1, %2, %3;" : "=l"(D) : "l"(A), "l"(B), "l"(C));
    return *reinterpret_cast<float2*>(&D);
}

// ------------------------- kernels -------------------------

// p_src[k][h] = sum_c W1[k, h*128+c] * att_src1[h,c]   (and p_dst)
__global__ void prep_kernel(const float* __restrict__ W1,
                            const float* __restrict__ as1,
                            const float* __restrict__ ad1) {
    int t = threadIdx.x;
    if (t >= 48) return;
    int which = t / 24;
    int r = t % 24;
    int k = r / 8, h = r % 8;
    const float* att = which ? ad1 : as1;
    float s = 0.f;
    for (int c = 0; c < 128; c++)
        s += W1[k * F1 + h * 128 + c] * att[h * 128 + c];
    (which ? g_pdst : g_psrc)[k * 8 + h] = s;
}

// build node features + zero degree
__global__ void node_kernel(const float* __restrict__ actions,
                            const float* __restrict__ nodef) {
    int n = blockIdx.x * blockDim.x + threadIdx.x;
    if (n >= NT) return;
    float ax = actions[n * 2 + 0];
    float ay = actions[n * 2 + 1];
    float nf = nodef[n];                 // [B,1,N] flat == n
    g_xf[n] = make_float4(ax, ay, nf, 0.f);
    g_deg[n] = 0;
}

__global__ void degree_kernel(const int* __restrict__ EI) {
    int e = blockIdx.x * blockDim.x + threadIdx.x;
    if (e >= ETOT) return;
    int src, dst;
    edge_sd(e, EI, src, dst);
    atomicAdd(&g_deg[dst], 1);
}

__global__ void scan_kernel() {
    __shared__ int sdata[1024];
    int t = threadIdx.x;
    int base = t * 16;
    int vals[16];
    int local = 0;
    #pragma unroll
    for (int i = 0; i < 16; i++) {
        int idx = base + i;
        int v = (idx < NT) ? g_deg[idx] : 0;
        vals[i] = local;
        local += v;
    }
    sdata[t] = local;
    __syncthreads();
    for (int off = 1; off < 1024; off <<= 1) {
        int v = (t >= off) ? sdata[t - off] : 0;
        __syncthreads();
        sdata[t] += v;
        __syncthreads();
    }
    int excl = (t == 0) ? 0 : sdata[t - 1];
    #pragma unroll
    for (int i = 0; i < 16; i++) {
        int idx = base + i;
        if (idx < NT) {
            int rp = excl + vals[i];
            g_rowptr[idx] = rp;
            g_cursor[idx] = rp;
        }
    }
    if (t == 1023) g_rowptr[NT] = sdata[1023];
}

__global__ void scatter_kernel(const int* __restrict__ EI) {
    int e = blockIdx.x * blockDim.x + threadIdx.x;
    if (e >= ETOT) return;
    int src, dst;
    edge_sd(e, EI, src, dst);
    int pos = atomicAdd(&g_cursor[dst], 1);
    g_csr_src[pos] = src;
}

// Single-pass conv1 attention: 8 lanes per destination, all 8 heads fused.
// No max-subtraction (logits bounded, exp is safe in fp32; softmax identical).
// s[d][h][k] = (sum_e exp(leaky(a_src+a_dst)) * x[src_e][k]) / (sum_e exp(...))
__global__ __launch_bounds__(256) void conv1_attn_kernel() {
    __shared__ float sps[24], spd[24];
    if (threadIdx.x < 24) {
        sps[threadIdx.x] = g_psrc[threadIdx.x];
        spd[threadIdx.x] = g_pdst[threadIdx.x];
    }
    __syncthreads();
    int gid = blockIdx.x * blockDim.x + threadIdx.x;
    int d = gid >> 3;                   // 8 lanes per dst; grid sized so d < NT always
    int sub = threadIdx.x & 7;

    float ps0[8], ps1[8], ps2[8];
    #pragma unroll
    for (int h = 0; h < 8; h++) { ps0[h] = sps[h]; ps1[h] = sps[8 + h]; ps2[h] = sps[16 + h]; }

    float4 xd = g_xf[d];
    float ad[8];
    #pragma unroll
    for (int h = 0; h < 8; h++)
        ad[h] = fmaf(xd.x, spd[h], fmaf(xd.y, spd[8 + h], xd.z * spd[16 + h]));

    int start = g_rowptr[d];
    int deg = g_rowptr[d + 1] - start;

    float se[8], sx[8], sy[8], sz[8];
    #pragma unroll
    for (int h = 0; h < 8; h++) { se[h] = 0.f; sx[h] = 0.f; sy[h] = 0.f; sz[h] = 0.f; }

    for (int e = sub; e < deg; e += 8) {
        int s = g_csr_src[start + e];
        float4 x = g_xf[s];
        #pragma unroll
        for (int h = 0; h < 8; h++) {
            float a = fmaf(x.x, ps0[h], fmaf(x.y, ps1[h], x.z * ps2[h]));
            float ea = __expf(leaky(a + ad[h]));
            se[h] += ea;
            sx[h] = fmaf(ea, x.x, sx[h]);
            sy[h] = fmaf(ea, x.y, sy[h]);
            sz[h] = fmaf(ea, x.z, sz[h]);
        }
    }
    // reduce within the 8-lane group (xor 4,2,1 stays inside aligned groups)
    #pragma unroll
    for (int o = 4; o > 0; o >>= 1) {
        #pragma unroll
        for (int h = 0; h < 8; h++) {
            se[h] += __shfl_xor_sync(0xffffffffu, se[h], o);
            sx[h] += __shfl_xor_sync(0xffffffffu, sx[h], o);
            sy[h] += __shfl_xor_sync(0xffffffffu, sy[h], o);
            sz[h] += __shfl_xor_sync(0xffffffffu, sz[h], o);
        }
    }
    if (sub == 0) {
        #pragma unroll
        for (int h = 0; h < 8; h++) {
            float inv = 1.0f / se[h];
            g_s[d * 24 + h * 3 + 0] = sx[h] * inv;
            g_s[d * 24 + h * 3 + 1] = sy[h] * inv;
            g_s[d * 24 + h * 3 + 2] = sz[h] * inv;
        }
    }
}

// Fused expand + GEMM:  h2 = (elu(s @ W1 + b1)) @ W2
// x1 tile computed on the fly in smem (never materialized in GMEM).
// Inner product uses packed fp32x2 FMA for 2x fp32 throughput.
__global__ __launch_bounds__(256) void fgemm_kernel(const float* __restrict__ W1,
                                                    const float* __restrict__ b1,
                                                    const float* __restrict__ W2) {
    __shared__ float  sW1[3 * F1];       // 12 KB
    __shared__ float  sB1[F1];           // 4 KB
    __shared__ float  sS[64 * 24];       // 6 KB
    __shared__ float2 sA[64][33];        // x1 tile, value duplicated in both halves (17 KB)
    __shared__ float  sB[32][EMBn];      // W2 chunk (8 KB)

    int tid = threadIdx.x;
    int row0 = blockIdx.x * 64;

    for (int i = tid; i < 3 * F1; i += 256) sW1[i] = W1[i];
    for (int i = tid; i < F1; i += 256)     sB1[i] = b1[i];
    for (int i = tid; i < 64 * 24; i += 256) sS[i] = g_s[row0 * 24 + i];

    int tx = tid % 16, ty = tid / 16;
    int br = tid >> 2;             // build row 0..63
    int bc0 = (tid & 3) * 8;       // build col base within chunk

    float2 acc[4][2];
    #pragma unroll
    for (int i = 0; i < 4; i++) { acc[i][0] = make_float2(0.f, 0.f); acc[i][1] = make_float2(0.f, 0.f); }

    for (int kc = 0; kc < F1; kc += 32) {
        __syncthreads();
        // build x1 tile chunk: 64 rows x 32 cols
        {
            int h = kc >> 7;                       // head constant within 32-chunk
            float s0 = sS[br * 24 + h * 3 + 0];
            float s1 = sS[br * 24 + h * 3 + 1];
            float s2 = sS[br * 24 + h * 3 + 2];
            #pragma unroll
            for (int i = 0; i < 8; i++) {
                int col = kc + bc0 + i;
                float v = fmaf(s0, sW1[col], fmaf(s1, sW1[F1 + col], fmaf(s2, sW1[2 * F1 + col], sB1[col])));
                v = elu(v);
                sA[br][bc0 + i] = make_float2(v, v);
            }
        }
        // load W2 chunk [32 x 64]
        {
            int q0 = tid * 2;
            #pragma unroll
            for (int t = 0; t < 2; t++) {
                int q = q0 + t;                    // 0..511 float4 slots
                int k = q >> 4, c4 = (q & 15) * 4;
                *(float4*)&sB[k][c4] = *(const float4*)&W2[(kc + k) * EMBn + c4];
            }
        }
        __syncthreads();
        #pragma unroll
        for (int kk = 0; kk < 32; kk++) {
            float4 b = *(const float4*)&sB[kk][tx * 4];
            float2 b01 = make_float2(b.x, b.y);
            float2 b23 = make_float2(b.z, b.w);
            #pragma unroll
            for (int i = 0; i < 4; i++) {
                float2 a = sA[ty * 4 + i][kk];
                acc[i][0] = ffma2(a, b01, acc[i][0]);
                acc[i][1] = ffma2(a, b23, acc[i][1]);
            }
        }
    }
    #pragma unroll
    for (int i = 0; i < 4; i++) {
        int r = row0 + ty * 4 + i;
        g_h2[r * EMBn + tx * 4 + 0] = acc[i][0].x;
        g_h2[r * EMBn + tx * 4 + 1] = acc[i][0].y;
        g_h2[r * EMBn + tx * 4 + 2] = acc[i][1].x;
        g_h2[r * EMBn + tx * 4 + 3] = acc[i][1].y;
    }
}

// a2s[n] = h2[n] . att_src2 ; a2d[n] = h2[n] . att_dst2   (warp per node)
__global__ void attn2_kernel(const float* __restrict__ as2, const float* __restrict__ ad2) {
    int wg = (blockIdx.x * blockDim.x + threadIdx.x) >> 5;
    if (wg >= NT) return;
    int lane = threadIdx.x & 31;
    float v0 = g_h2[wg * 64 + lane];
    float v1 = g_h2[wg * 64 + 32 + lane];
    float ss = v0 * as2[lane] + v1 * as2[32 + lane];
    float sd = v0 * ad2[lane] + v1 * ad2[32 + lane];
    ss = warp_sum(ss);
    sd = warp_sum(sd);
    if (lane == 0) { g_a2s[wg] = ss; g_a2d[wg] = sd; }
}

// Single-pass per-dst softmax + aggregation of h2, fused elu(+b2) -> x2
__global__ void conv2_agg_kernel(const float* __restrict__ b2) {
    __shared__ float wbuf[8][128];
    __shared__ int   ibuf[8][128];
    int wg = (blockIdx.x * blockDim.x + threadIdx.x) >> 5;
    if (wg >= NT) return;
    int lane = threadIdx.x & 31;
    int w = (threadIdx.x >> 5) & 7;
    int d = wg;
    int start = g_rowptr[d];
    int deg = g_rowptr[d + 1] - start;
    float adv = g_a2d[d];
    float se = 0.f, acc0 = 0.f, acc1 = 0.f;
    for (int base = 0; base < deg; base += 128) {
        int cnt = min(128, deg - base);
        for (int e = lane; e < cnt; e += 32) {
            int s = g_csr_src[start + base + e];
            float ea = __expf(leaky(g_a2s[s] + adv));
            wbuf[w][e] = ea;
            ibuf[w][e] = s;
            se += ea;
        }
        __syncwarp();
        #pragma unroll 4
        for (int e = 0; e < cnt; e++) {
            float ea = wbuf[w][e];
            int s = ibuf[w][e];
            acc0 += ea * g_h2[s * 64 + lane];
            acc1 += ea * g_h2[s * 64 + 32 + lane];
        }
        __syncwarp();
    }
    se = warp_sum(se);
    float inv = 1.0f / se;
    float r0 = acc0 * inv + b2[lane];
    float r1 = acc1 * inv + b2[32 + lane];
    g_x2[d * 64 + lane]      = elu(r0);
    g_x2[d * 64 + 32 + lane] = elu(r1);
}

// split-K stage 1: partial[c][b][j] = sum_{k in chunk} x2flat[b][k] * mw1[k][j]
__global__ void mlp1_stage1(const float* __restrict__ mw1) {
    int c = blockIdx.x;
    int j = threadIdx.x & 127;
    int bh = threadIdx.x >> 7;       // 0/1 -> b halves
    int k0 = c * CKs;
    float acc[8] = {0, 0, 0, 0, 0, 0, 0, 0};
    const float* xb = g_x2 + bh * 8 * 64000 + k0;   // flat [16][64000]
    for (int k = 0; k < CKs; k++) {
        float wv = mw1[(k0 + k) * HIDn + j];
        #pragma unroll
        for (int b = 0; b < 8; b++)
            acc[b] += xb[b * 64000 + k] * wv;
    }
    #pragma unroll
    for (int b = 0; b < 8; b++)
        g_part[(c * 16 + bh * 8 + b) * HIDn + j] = acc[b];
}

__global__ void mlp1_reduce(const float* __restrict__ mb1) {
    int idx = blockIdx.x * blockDim.x + threadIdx.x;
    if (idx >= 16 * HIDn) return;
    int b = idx >> 7, j = idx & 127;
    float s = 0.f;
    for (int c = 0; c < NCHUNK; c++)
        s += g_part[(c * 16 + b) * HIDn + j];
    s += mb1[j];
    g_y1[b * HIDn + j] = fmaxf(s, 0.f);
}

__global__ void mlp2_kernel(const float* __restrict__ mw2, const float* __restrict__ mb2) {
    __shared__ float ys[16 * HIDn];
    int tid = threadIdx.x;
    for (int i = tid; i < 16 * HIDn; i += 128) ys[i] = g_y1[i];
    __syncthreads();
    int j = tid;
    float acc[16];
    #pragma unroll
    for (int b = 0; b < 16; b++) acc[b] = 0.f;
    for (int k = 0; k < HIDn; k++) {
        float wv = mw2[k * HIDn + j];
        #pragma unroll
        for (int b = 0; b < 16; b++)
            acc[b] += ys[b * HIDn + k] * wv;
    }
    #pragma unroll
    for (int b = 0; b < 16; b++)
        g_y2[b * HIDn + j] = fmaxf(acc[b] + mb2[j], 0.f);
}

__global__ void out_kernel(const float* __restrict__ ow, const float* __restrict__ ob,
                           float* __restrict__ out) {
    __shared__ float ys[16 * HIDn];
    int tid = threadIdx.x;
    for (int i = tid; i < 16 * HIDn; i += 128) ys[i] = g_y2[i];
    __syncthreads();
    int j = blockIdx.x * 128 + tid;
    if (j >= Nn) return;
    float acc[16];
    #pragma unroll
    for (int b = 0; b < 16; b++) acc[b] = 0.f;
    for (int k = 0; k < HIDn; k++) {
        float wv = ow[k * Nn + j];
        #pragma unroll
        for (int b = 0; b < 16; b++)
            acc[b] += ys[b * HIDn + k] * wv;
    }
    #pragma unroll
    for (int b = 0; b < 16; b++) {
        float v = acc[b] + ob[j];
        out[b * Nn + j] = 1.0f / (1.0f + __expf(-v));
    }
}

// ------------------------- launch -------------------------
extern "C" void kernel_launch(void* const* d_in, const int* in_sizes, int n_in,
                              void* d_out, int out_size) {
    const float* actions = (const float*)d_in[0];
    const float* nodef   = (const float*)d_in[1];
    const int*   ei      = (const int*)d_in[2];
    const float* W1  = (const float*)d_in[3];
    const float* as1 = (const float*)d_in[4];
    const float* ad1 = (const float*)d_in[5];
    const float* b1  = (const float*)d_in[6];
    const float* W2  = (const float*)d_in[7];
    const float* as2 = (const float*)d_in[8];
    const float* ad2 = (const float*)d_in[9];
    const float* b2  = (const float*)d_in[10];
    const float* mw1 = (const float*)d_in[11];
    const float* mb1 = (const float*)d_in[12];
    const float* mw2 = (const float*)d_in[13];
    const float* mb2 = (const float*)d_in[14];
    const float* ow  = (const float*)d_in[15];
    const float* ob  = (const float*)d_in[16];
    float* out = (float*)d_out;

    node_kernel<<<(NT + 255) / 256, 256>>>(actions, nodef);
    prep_kernel<<<1, 64>>>(W1, as1, ad1);
    degree_kernel<<<(ETOT + 255) / 256, 256>>>(ei);
    scan_kernel<<<1, 1024>>>();
    scatter_kernel<<<(ETOT + 255) / 256, 256>>>(ei);
    conv1_attn_kernel<<<NT * 8 / 256, 256>>>();      // 8 lanes per dst
    fgemm_kernel<<<NT / 64, 256>>>(W1, b1, W2);
    attn2_kernel<<<NT / 8, 256>>>(as2, ad2);
    conv2_agg_kernel<<<NT / 8, 256>>>(b2);
    mlp1_stage1<<<NCHUNK, 256>>>(mw1);
    mlp1_reduce<<<8, 256>>>(mb1);
    mlp2_kernel<<<1, 128>>>(mw2, mb2);
    out_kernel<<<8, 128>>>(ow, ob, out);
}

// round 5
// speedup vs baseline: 1.7241x; 1.1531x over previous
#include <cuda_runtime.h>
#include <math.h>

#define Bn 16
#define Nn 1000
#define En 16000
#define NT 16000          /* Bn*Nn total nodes  */
#define EBASE 256000      /* Bn*En edges before self loops */
#define ETOT 272000       /* + NT self loops */
#define TWOE 32000
#define HALFB 8

#define H1n 8
#define F1 1024           /* H1*C1 */
#define EMBn 64
#define HIDn 128

// ------------------------- scratch (static, no allocs) -------------------------
__device__ __align__(16) float4 g_xf[NT];           // node features (x,y,nf,0)
__device__ float g_psrc[24];                         // [3][8]
__device__ float g_pdst[24];
__device__ __align__(16) int   g_deg[16384];         // padded for int4
__device__ __align__(16) int   g_rowptr[NT + 4];
__device__ __align__(16) int   g_cursor[NT + 4];
__device__ int   g_csr_src[ETOT];
__device__ float g_s[NT * 24];                       // [NT][8][3]
__device__ __align__(16) float g_h2[NT * EMBn];
__device__ float g_a2s[NT];
__device__ float g_a2d[NT];
__device__ __align__(16) float g_x2[NT * EMBn];
#define NCHUNK 128
#define CKs 500
__device__ float g_part[NCHUNK * 16 * HIDn];
__device__ float g_y1[16 * HIDn];
__device__ float g_y2[16 * HIDn];

// ------------------------- helpers -------------------------
__device__ __forceinline__ void edge_sd(int e, const int* __restrict__ EI, int& src, int& dst) {
    if (e < EBASE) {
        int b   = e / TWOE;          // graph providing src (0..7)
        int rem = e - b * TWOE;      // r*E + j
        src = EI[b * TWOE + rem] + b * Nn;
        int b2 = b + HALFB;          // graph providing dst (8..15)
        dst = EI[b2 * TWOE + rem] + b2 * Nn;
    } else {
        src = dst = e - EBASE;       // self loop
    }
}

__device__ __forceinline__ float warp_sum(float v) {
    #pragma unroll
    for (int o = 16; o > 0; o >>= 1) v += __shfl_xor_sync(0xffffffffu, v, o);
    return v;
}
__device__ __forceinline__ float leaky(float v) { return v > 0.f ? v : 0.2f * v; }
__device__ __forceinline__ float elu(float v)   { return v > 0.f ? v : (__expf(v) - 1.0f); }

// packed fp32x2 FMA (sm_100+): d = a*b + c on both lanes
__device__ __forceinline__ float2 ffma2(float2 a, float2 b, float2 c) {
    unsigned long long A = *reinterpret_cast<unsigned long long*>(&a);
    unsigned long long B = *reinterpret_cast<unsigned long long*>(&b);
    unsigned long long C = *reinterpret_cast<unsigned long long*>(&c);
    unsigned long long D;
    asm("fma.rn.f32x2 %0, %1, %2, %3;" : "=l"(D) : "l"(A), "l"(B), "l"(C));
    return *reinterpret_cast<float2*>(&D);
}

// ------------------------- kernels -------------------------

// node features + deg zero; last block computes attention projections
__global__ void node_kernel(const float* __restrict__ actions,
                            const float* __restrict__ nodef,
                            const float* __restrict__ W1,
                            const float* __restrict__ as1,
                            const float* __restrict__ ad1) {
    if (blockIdx.x == 63) {
        int t = threadIdx.x;
        if (t < 48) {
            int which = t / 24;
            int r = t % 24;
            int k = r / 8, h = r % 8;
            const float* att = which ? ad1 : as1;
            float s = 0.f;
            for (int c = 0; c < 128; c++)
                s += W1[k * F1 + h * 128 + c] * att[h * 128 + c];
            (which ? g_pdst : g_psrc)[k * 8 + h] = s;
        }
        // also zero the deg padding tail
        if (t >= 48 && t < 48 + 384) {
            int i = NT + (t - 48);
            if (i < 16384) g_deg[i] = 0;
        }
        return;
    }
    int n = blockIdx.x * blockDim.x + threadIdx.x;
    if (n >= NT) return;
    float ax = actions[n * 2 + 0];
    float ay = actions[n * 2 + 1];
    float nf = nodef[n];                 // [B,1,N] flat == n
    g_xf[n] = make_float4(ax, ay, nf, 0.f);
    g_deg[n] = 0;
}

// 4 edges per thread -> 4 independent atomic chains
__global__ void degree_kernel(const int* __restrict__ EI) {
    int e0 = (blockIdx.x * blockDim.x + threadIdx.x) * 4;
    #pragma unroll
    for (int q = 0; q < 4; q++) {
        int e = e0 + q;
        if (e < ETOT) {
            int src, dst;
            edge_sd(e, EI, src, dst);
            atomicAdd(&g_deg[dst], 1);
        }
    }
}

// hierarchical shfl scan: 2 barriers total, int4 I/O
__global__ __launch_bounds__(1024) void scan_kernel() {
    __shared__ int warp_off[33];
    int t = threadIdx.x;
    int lane = t & 31, wid = t >> 5;
    int base4 = t * 4;                       // int4 index, covers 4096 int4 = 16384 ints
    int vals[16];
    int local = 0;
    int4 x[4];
    #pragma unroll
    for (int q = 0; q < 4; q++)
        x[q] = ((const int4*)g_deg)[base4 + q];   // tail padded with zeros
    #pragma unroll
    for (int q = 0; q < 4; q++) {
        vals[q * 4 + 0] = local; local += x[q].x;
        vals[q * 4 + 1] = local; local += x[q].y;
        vals[q * 4 + 2] = local; local += x[q].z;
        vals[q * 4 + 3] = local; local += x[q].w;
    }
    int inc = local;
    #pragma unroll
    for (int o = 1; o < 32; o <<= 1) {
        int nv = __shfl_up_sync(0xffffffffu, inc, o);
        if (lane >= o) inc += nv;
    }
    __shared__ int warp_tot[32];
    if (lane == 31) warp_tot[wid] = inc;
    __syncthreads();
    if (wid == 0) {
        int v = warp_tot[lane];
        int i2 = v;
        #pragma unroll
        for (int o = 1; o < 32; o <<= 1) {
            int nv = __shfl_up_sync(0xffffffffu, i2, o);
            if (lane >= o) i2 += nv;
        }
        warp_off[lane + 1] = i2;
        if (lane == 0) warp_off[0] = 0;
    }
    __syncthreads();
    int excl = warp_off[wid] + (inc - local);
    #pragma unroll
    for (int q = 0; q < 4; q++) {
        int idx4 = base4 + q;
        if (idx4 * 4 < NT) {
            int4 rp;
            rp.x = excl + vals[q * 4 + 0];
            rp.y = excl + vals[q * 4 + 1];
            rp.z = excl + vals[q * 4 + 2];
            rp.w = excl + vals[q * 4 + 3];
            ((int4*)g_rowptr)[idx4] = rp;
            ((int4*)g_cursor)[idx4] = rp;
        }
    }
    if (t == 0) g_rowptr[NT] = warp_off[32];
}

__global__ void scatter_kernel(const int* __restrict__ EI) {
    int e0 = (blockIdx.x * blockDim.x + threadIdx.x) * 4;
    #pragma unroll
    for (int q = 0; q < 4; q++) {
        int e = e0 + q;
        if (e < ETOT) {
            int src, dst;
            edge_sd(e, EI, src, dst);
            int pos = atomicAdd(&g_cursor[dst], 1);
            g_csr_src[pos] = src;
        }
    }
}

// Single-pass conv1 attention: 8 lanes per destination, all 8 heads fused.
__global__ __launch_bounds__(256) void conv1_attn_kernel() {
    __shared__ float sps[24], spd[24];
    if (threadIdx.x < 24) {
        sps[threadIdx.x] = g_psrc[threadIdx.x];
        spd[threadIdx.x] = g_pdst[threadIdx.x];
    }
    __syncthreads();
    int gid = blockIdx.x * blockDim.x + threadIdx.x;
    int d = gid >> 3;                   // 8 lanes per dst
    int sub = threadIdx.x & 7;

    float ps0[8], ps1[8], ps2[8];
    #pragma unroll
    for (int h = 0; h < 8; h++) { ps0[h] = sps[h]; ps1[h] = sps[8 + h]; ps2[h] = sps[16 + h]; }

    float4 xd = g_xf[d];
    float ad[8];
    #pragma unroll
    for (int h = 0; h < 8; h++)
        ad[h] = fmaf(xd.x, spd[h], fmaf(xd.y, spd[8 + h], xd.z * spd[16 + h]));

    int start = g_rowptr[d];
    int deg = g_rowptr[d + 1] - start;

    float se[8], sx[8], sy[8], sz[8];
    #pragma unroll
    for (int h = 0; h < 8; h++) { se[h] = 0.f; sx[h] = 0.f; sy[h] = 0.f; sz[h] = 0.f; }

    for (int e = sub; e < deg; e += 8) {
        int s = g_csr_src[start + e];
        float4 x = g_xf[s];
        #pragma unroll
        for (int h = 0; h < 8; h++) {
            float a = fmaf(x.x, ps0[h], fmaf(x.y, ps1[h], x.z * ps2[h]));
            float ea = __expf(leaky(a + ad[h]));
            se[h] += ea;
            sx[h] = fmaf(ea, x.x, sx[h]);
            sy[h] = fmaf(ea, x.y, sy[h]);
            sz[h] = fmaf(ea, x.z, sz[h]);
        }
    }
    #pragma unroll
    for (int o = 4; o > 0; o >>= 1) {
        #pragma unroll
        for (int h = 0; h < 8; h++) {
            se[h] += __shfl_xor_sync(0xffffffffu, se[h], o);
            sx[h] += __shfl_xor_sync(0xffffffffu, sx[h], o);
            sy[h] += __shfl_xor_sync(0xffffffffu, sy[h], o);
            sz[h] += __shfl_xor_sync(0xffffffffu, sz[h], o);
        }
    }
    if (sub == 0) {
        #pragma unroll
        for (int h = 0; h < 8; h++) {
            float inv = 1.0f / se[h];
            g_s[d * 24 + h * 3 + 0] = sx[h] * inv;
            g_s[d * 24 + h * 3 + 1] = sy[h] * inv;
            g_s[d * 24 + h * 3 + 2] = sz[h] * inv;
        }
    }
}

// Fused expand + GEMM + attn2 epilogue:
//   h2 = (elu(s @ W1 + b1)) @ W2 ;  a2s/a2d = h2 . att2  (from registers)
__global__ __launch_bounds__(256) void fgemm_kernel(const float* __restrict__ W1,
                                                    const float* __restrict__ b1,
                                                    const float* __restrict__ W2,
                                                    const float* __restrict__ as2,
                                                    const float* __restrict__ ad2) {
    __shared__ float  sW1[3 * F1];       // 12 KB
    __shared__ float  sB1[F1];           // 4 KB
    __shared__ float  sS[64 * 24];       // 6 KB
    __shared__ float2 sA[64][33];        // x1 tile, duplicated halves (17 KB)
    __shared__ float  sB[32][EMBn];      // W2 chunk (8 KB)

    int tid = threadIdx.x;
    int row0 = blockIdx.x * 64;

    for (int i = tid; i < 3 * F1; i += 256) sW1[i] = W1[i];
    for (int i = tid; i < F1; i += 256)     sB1[i] = b1[i];
    for (int i = tid; i < 64 * 24; i += 256) sS[i] = g_s[row0 * 24 + i];

    int tx = tid % 16, ty = tid / 16;
    int br = tid >> 2;             // build row 0..63
    int bc0 = (tid & 3) * 8;       // build col base within chunk

    float2 acc[4][2];
    #pragma unroll
    for (int i = 0; i < 4; i++) { acc[i][0] = make_float2(0.f, 0.f); acc[i][1] = make_float2(0.f, 0.f); }

    for (int kc = 0; kc < F1; kc += 32) {
        __syncthreads();
        {
            int h = kc >> 7;
            float s0 = sS[br * 24 + h * 3 + 0];
            float s1 = sS[br * 24 + h * 3 + 1];
            float s2 = sS[br * 24 + h * 3 + 2];
            #pragma unroll
            for (int i = 0; i < 8; i++) {
                int col = kc + bc0 + i;
                float v = fmaf(s0, sW1[col], fmaf(s1, sW1[F1 + col], fmaf(s2, sW1[2 * F1 + col], sB1[col])));
                v = elu(v);
                sA[br][bc0 + i] = make_float2(v, v);
            }
        }
        {
            int q0 = tid * 2;
            #pragma unroll
            for (int t = 0; t < 2; t++) {
                int q = q0 + t;
                int k = q >> 4, c4 = (q & 15) * 4;
                *(float4*)&sB[k][c4] = *(const float4*)&W2[(kc + k) * EMBn + c4];
            }
        }
        __syncthreads();
        #pragma unroll
        for (int kk = 0; kk < 32; kk++) {
            float4 b = *(const float4*)&sB[kk][tx * 4];
            float2 b01 = make_float2(b.x, b.y);
            float2 b23 = make_float2(b.z, b.w);
            #pragma unroll
            for (int i = 0; i < 4; i++) {
                float2 a = sA[ty * 4 + i][kk];
                acc[i][0] = ffma2(a, b01, acc[i][0]);
                acc[i][1] = ffma2(a, b23, acc[i][1]);
            }
        }
    }
    // store h2
    #pragma unroll
    for (int i = 0; i < 4; i++) {
        int r = row0 + ty * 4 + i;
        g_h2[r * EMBn + tx * 4 + 0] = acc[i][0].x;
        g_h2[r * EMBn + tx * 4 + 1] = acc[i][0].y;
        g_h2[r * EMBn + tx * 4 + 2] = acc[i][1].x;
        g_h2[r * EMBn + tx * 4 + 3] = acc[i][1].y;
    }
    // attn2 epilogue: reduce h2 . att2 over tx (lane bits 0-3)
    float4 a_s = *(const float4*)&as2[tx * 4];
    float4 a_d = *(const float4*)&ad2[tx * 4];
    #pragma unroll
    for (int i = 0; i < 4; i++) {
        float ss = acc[i][0].x * a_s.x + acc[i][0].y * a_s.y + acc[i][1].x * a_s.z + acc[i][1].y * a_s.w;
        float sd = acc[i][0].x * a_d.x + acc[i][0].y * a_d.y + acc[i][1].x * a_d.z + acc[i][1].y * a_d.w;
        #pragma unroll
        for (int o = 1; o < 16; o <<= 1) {
            ss += __shfl_xor_sync(0xffffffffu, ss, o);
            sd += __shfl_xor_sync(0xffffffffu, sd, o);
        }
        if (tx == 0) {
            g_a2s[row0 + ty * 4 + i] = ss;
            g_a2d[row0 + ty * 4 + i] = sd;
        }
    }
}

// Single-pass per-dst softmax + aggregation of h2, fused elu(+b2) -> x2 (float2)
__global__ void conv2_agg_kernel(const float* __restrict__ b2) {
    __shared__ float wbuf[8][128];
    __shared__ int   ibuf[8][128];
    int wg = (blockIdx.x * blockDim.x + threadIdx.x) >> 5;
    if (wg >= NT) return;
    int lane = threadIdx.x & 31;
    int w = (threadIdx.x >> 5) & 7;
    int d = wg;
    int start = g_rowptr[d];
    int deg = g_rowptr[d + 1] - start;
    float adv = g_a2d[d];
    float se = 0.f;
    float2 acc = make_float2(0.f, 0.f);
    for (int base = 0; base < deg; base += 128) {
        int cnt = min(128, deg - base);
        for (int e = lane; e < cnt; e += 32) {
            int s = g_csr_src[start + base + e];
            float ea = __expf(leaky(g_a2s[s] + adv));
            wbuf[w][e] = ea;
            ibuf[w][e] = s;
            se += ea;
        }
        __syncwarp();
        #pragma unroll 4
        for (int e = 0; e < cnt; e++) {
            float ea = wbuf[w][e];
            int s = ibuf[w][e];
            float2 v = ((const float2*)(g_h2 + s * 64))[lane];
            acc.x = fmaf(ea, v.x, acc.x);
            acc.y = fmaf(ea, v.y, acc.y);
        }
        __syncwarp();
    }
    se = warp_sum(se);
    float inv = 1.0f / se;
    float2 bb = ((const float2*)b2)[lane];
    float2 r;
    r.x = elu(acc.x * inv + bb.x);
    r.y = elu(acc.y * inv + bb.y);
    ((float2*)(g_x2 + d * 64))[lane] = r;
}

// split-K stage 1: partial[c][b][j] = sum_{k in chunk} x2flat[b][k] * mw1[k][j]
__global__ void mlp1_stage1(const float* __restrict__ mw1) {
    int c = blockIdx.x;
    int j = threadIdx.x & 127;
    int bh = threadIdx.x >> 7;       // 0/1 -> b halves
    int k0 = c * CKs;
    float acc[8] = {0, 0, 0, 0, 0, 0, 0, 0};
    const float* xb = g_x2 + bh * 8 * 64000 + k0;   // flat [16][64000]
    #pragma unroll 4
    for (int k = 0; k < CKs; k++) {
        float wv = mw1[(k0 + k) * HIDn + j];
        #pragma unroll
        for (int b = 0; b < 8; b++)
            acc[b] = fmaf(xb[b * 64000 + k], wv, acc[b]);
    }
    #pragma unroll
    for (int b = 0; b < 8; b++)
        g_part[(c * 16 + bh * 8 + b) * HIDn + j] = acc[b];
}

__global__ void mlp1_reduce(const float* __restrict__ mb1) {
    int idx = blockIdx.x * blockDim.x + threadIdx.x;
    if (idx >= 16 * HIDn) return;
    int b = idx >> 7, j = idx & 127;
    float s = 0.f;
    #pragma unroll 4
    for (int c = 0; c < NCHUNK; c++)
        s += g_part[(c * 16 + b) * HIDn + j];
    s += mb1[j];
    g_y1[b * HIDn + j] = fmaxf(s, 0.f);
}

__global__ void mlp2_kernel(const float* __restrict__ mw2, const float* __restrict__ mb2) {
    __shared__ float ys[16 * HIDn];
    int tid = threadIdx.x;
    for (int i = tid; i < 16 * HIDn; i += 128) ys[i] = g_y1[i];
    __syncthreads();
    int j = tid;
    float acc[16];
    #pragma unroll
    for (int b = 0; b < 16; b++) acc[b] = 0.f;
    #pragma unroll 4
    for (int k = 0; k < HIDn; k++) {
        float wv = mw2[k * HIDn + j];
        #pragma unroll
        for (int b = 0; b < 16; b++)
            acc[b] = fmaf(ys[b * HIDn + k], wv, acc[b]);
    }
    #pragma unroll
    for (int b = 0; b < 16; b++)
        g_y2[b * HIDn + j] = fmaxf(acc[b] + mb2[j], 0.f);
}

// 16 blocks x 128 threads: 64 j-columns per block, 2 b-halves
__global__ void out_kernel(const float* __restrict__ ow, const float* __restrict__ ob,
                           float* __restrict__ out) {
    __shared__ float ys[16 * HIDn];
    int tid = threadIdx.x;
    for (int i = tid; i < 16 * HIDn; i += 128) ys[i] = g_y2[i];
    __syncthreads();
    int j = blockIdx.x * 64 + (tid & 63);
    int bh = tid >> 6;                 // 0/1 -> b base 0/8
    if (j >= Nn) return;
    float acc[8];
    #pragma unroll
    for (int b = 0; b < 8; b++) acc[b] = 0.f;
    const float* y = ys + bh * 8 * HIDn;
    #pragma unroll 4
    for (int k = 0; k < HIDn; k++) {
        float wv = ow[k * Nn + j];
        #pragma unroll
        for (int b = 0; b < 8; b++)
            acc[b] = fmaf(y[b * HIDn + k], wv, acc[b]);
    }
    float obj = ob[j];
    #pragma unroll
    for (int b = 0; b < 8; b++) {
        float v = acc[b] + obj;
        out[(bh * 8 + b) * Nn + j] = 1.0f / (1.0f + __expf(-v));
    }
}

// ------------------------- launch -------------------------
extern "C" void kernel_launch(void* const* d_in, const int* in_sizes, int n_in,
                              void* d_out, int out_size) {
    const float* actions = (const float*)d_in[0];
    const float* nodef   = (const float*)d_in[1];
    const int*   ei      = (const int*)d_in[2];
    const float* W1  = (const float*)d_in[3];
    const float* as1 = (const float*)d_in[4];
    const float* ad1 = (const float*)d_in[5];
    const float* b1  = (const float*)d_in[6];
    const float* W2  = (const float*)d_in[7];
    const float* as2 = (const float*)d_in[8];
    const float* ad2 = (const float*)d_in[9];
    const float* b2  = (const float*)d_in[10];
    const float* mw1 = (const float*)d_in[11];
    const float* mb1 = (const float*)d_in[12];
    const float* mw2 = (const float*)d_in[13];
    const float* mb2 = (const float*)d_in[14];
    const float* ow  = (const float*)d_in[15];
    const float* ob  = (const float*)d_in[16];
    float* out = (float*)d_out;

    node_kernel<<<64, 256>>>(actions, nodef, W1, as1, ad1);   // 63 node blocks + 1 prep block
    degree_kernel<<<(ETOT / 4 + 255) / 256, 256>>>(ei);
    scan_kernel<<<1, 1024>>>();
    scatter_kernel<<<(ETOT / 4 + 255) / 256, 256>>>(ei);
    conv1_attn_kernel<<<NT * 8 / 256, 256>>>();
    fgemm_kernel<<<NT / 64, 256>>>(W1, b1, W2, as2, ad2);
    conv2_agg_kernel<<<NT / 8, 256>>>(b2);
    mlp1_stage1<<<NCHUNK, 256>>>(mw1);
    mlp1_reduce<<<8, 256>>>(mb1);
    mlp2_kernel<<<1, 128>>>(mw2, mb2);
    out_kernel<<<16, 128>>>(ow, ob, out);
}

// round 6
// speedup vs baseline: 1.7974x; 1.0425x over previous
#include <cuda_runtime.h>
#include <math.h>

#define Bn 16
#define Nn 1000
#define En 16000
#define NT 16000          /* Bn*Nn total nodes  */
#define EBASE 256000      /* Bn*En edges before self loops */
#define ETOT 272000       /* + NT self loops */
#define TWOE 32000
#define HALFB 8

#define H1n 8
#define F1 1024           /* H1*C1 */
#define EMBn 64
#define HIDn 128

#define NCHUNK 400
#define CK 160            /* 400*160 = 64000 */

// ------------------------- scratch (static, no allocs) -------------------------
__device__ __align__(16) float4 g_xf[NT];           // node features (x,y,nf,0)
__device__ float g_psrc[24];                         // [3][8]
__device__ float g_pdst[24];
__device__ __align__(16) int   g_deg[16384];         // padded for int4; zero at load, re-zeroed by conv1
__device__ __align__(16) int   g_rowptr[NT + 4];
__device__ __align__(16) int   g_cursor[NT + 4];
__device__ int   g_csr_src[ETOT];
__device__ float g_s[NT * 24];                       // [NT][8][3]
__device__ __align__(16) float g_h2[NT * EMBn];
__device__ float g_a2s[NT];
__device__ float g_a2d[NT];
__device__ __align__(16) float g_x2t[64000 * 16];    // transposed: [k=(n*64+c)][b]
__device__ float g_part[NCHUNK * 16 * HIDn];         // 3.3 MB
__device__ float g_y1[16 * HIDn];
__device__ float g_y2[16 * HIDn];

// ------------------------- helpers -------------------------
__device__ __forceinline__ void edge_sd(int e, const int* __restrict__ EI, int& src, int& dst) {
    if (e < EBASE) {
        int b   = e / TWOE;          // graph providing src (0..7)
        int rem = e - b * TWOE;      // r*E + j
        src = EI[b * TWOE + rem] + b * Nn;
        int b2 = b + HALFB;          // graph providing dst (8..15)
        dst = EI[b2 * TWOE + rem] + b2 * Nn;
    } else {
        src = dst = e - EBASE;       // self loop
    }
}

__device__ __forceinline__ float warp_sum(float v) {
    #pragma unroll
    for (int o = 16; o > 0; o >>= 1) v += __shfl_xor_sync(0xffffffffu, v, o);
    return v;
}
__device__ __forceinline__ float leaky(float v) { return v > 0.f ? v : 0.2f * v; }

// FMA-pipe exp: exp(x) = 2^(x*log2e), degree-7 Taylor for 2^f on [0,1),
// exponent applied via integer bit trick. No MUFU. rel err ~7e-7.
__device__ __forceinline__ float fexp(float x) {
    float t = x * 1.4426950408889634f;
    t = fmaxf(fminf(t, 126.0f), -126.0f);
    int ni = __float2int_rd(t);            // floor
    float f = t - (float)ni;
    float p = 1.52526e-5f;
    p = fmaf(p, f, 1.54033e-4f);
    p = fmaf(p, f, 1.33336e-3f);
    p = fmaf(p, f, 9.61813e-3f);
    p = fmaf(p, f, 5.55041e-2f);
    p = fmaf(p, f, 2.40227e-1f);
    p = fmaf(p, f, 6.93147e-1f);
    p = fmaf(p, f, 1.0f);
    float s = __int_as_float((ni + 127) << 23);
    return s * p;
}
__device__ __forceinline__ float elu(float v) {
    float e = fexp(fminf(v, 0.f)) - 1.0f;
    return v > 0.f ? v : e;
}

// packed fp32x2 FMA (sm_100+)
__device__ __forceinline__ float2 ffma2(float2 a, float2 b, float2 c) {
    unsigned long long A = *reinterpret_cast<unsigned long long*>(&a);
    unsigned long long B = *reinterpret_cast<unsigned long long*>(&b);
    unsigned long long C = *reinterpret_cast<unsigned long long*>(&c);
    unsigned long long D;
    asm("fma.rn.f32x2 %0, %1, %2, %3;" : "=l"(D) : "l"(A), "l"(B), "l"(C));
    return *reinterpret_cast<float2*>(&D);
}

// ------------------------- kernels -------------------------

// Fused: node features (blocks 0-62) + prep projections (block 63) + degree count (blocks 64+)
// g_deg was zeroed by previous replay's conv1_attn (module-load zero the first time).
__global__ void nd_kernel(const float* __restrict__ actions,
                          const float* __restrict__ nodef,
                          const float* __restrict__ W1,
                          const float* __restrict__ as1,
                          const float* __restrict__ ad1,
                          const int* __restrict__ EI) {
    int blk = blockIdx.x;
    if (blk < 63) {
        int n = blk * 256 + threadIdx.x;
        if (n >= NT) return;
        float ax = actions[n * 2 + 0];
        float ay = actions[n * 2 + 1];
        float nf = nodef[n];
        g_xf[n] = make_float4(ax, ay, nf, 0.f);
    } else if (blk == 63) {
        int t = threadIdx.x;
        if (t < 48) {
            int which = t / 24;
            int r = t % 24;
            int k = r / 8, h = r % 8;
            const float* att = which ? ad1 : as1;
            float s = 0.f;
            for (int c = 0; c < 128; c++)
                s += W1[k * F1 + h * 128 + c] * att[h * 128 + c];
            (which ? g_pdst : g_psrc)[k * 8 + h] = s;
        }
    } else {
        int idx = (blk - 64) * 256 + threadIdx.x;
        #pragma unroll
        for (int q = 0; q < 2; q++) {
            int e = idx * 2 + q;
            if (e < ETOT) {
                int src, dst;
                edge_sd(e, EI, src, dst);
                atomicAdd(&g_deg[dst], 1);
            }
        }
    }
}

// hierarchical shfl scan: 2 barriers total, int4 I/O
__global__ __launch_bounds__(1024) void scan_kernel() {
    __shared__ int warp_off[33];
    __shared__ int warp_tot[32];
    int t = threadIdx.x;
    int lane = t & 31, wid = t >> 5;
    int base4 = t * 4;
    int vals[16];
    int local = 0;
    int4 x[4];
    #pragma unroll
    for (int q = 0; q < 4; q++)
        x[q] = ((const int4*)g_deg)[base4 + q];
    #pragma unroll
    for (int q = 0; q < 4; q++) {
        vals[q * 4 + 0] = local; local += x[q].x;
        vals[q * 4 + 1] = local; local += x[q].y;
        vals[q * 4 + 2] = local; local += x[q].z;
        vals[q * 4 + 3] = local; local += x[q].w;
    }
    int inc = local;
    #pragma unroll
    for (int o = 1; o < 32; o <<= 1) {
        int nv = __shfl_up_sync(0xffffffffu, inc, o);
        if (lane >= o) inc += nv;
    }
    if (lane == 31) warp_tot[wid] = inc;
    __syncthreads();
    if (wid == 0) {
        int i2 = warp_tot[lane];
        #pragma unroll
        for (int o = 1; o < 32; o <<= 1) {
            int nv = __shfl_up_sync(0xffffffffu, i2, o);
            if (lane >= o) i2 += nv;
        }
        warp_off[lane + 1] = i2;
        if (lane == 0) warp_off[0] = 0;
    }
    __syncthreads();
    int excl = warp_off[wid] + (inc - local);
    #pragma unroll
    for (int q = 0; q < 4; q++) {
        int idx4 = base4 + q;
        if (idx4 * 4 < NT) {
            int4 rp;
            rp.x = excl + vals[q * 4 + 0];
            rp.y = excl + vals[q * 4 + 1];
            rp.z = excl + vals[q * 4 + 2];
            rp.w = excl + vals[q * 4 + 3];
            ((int4*)g_rowptr)[idx4] = rp;
            ((int4*)g_cursor)[idx4] = rp;
        }
    }
    if (t == 0) g_rowptr[NT] = warp_off[32];
}

__global__ void scatter_kernel(const int* __restrict__ EI) {
    int idx = blockIdx.x * blockDim.x + threadIdx.x;
    #pragma unroll
    for (int q = 0; q < 2; q++) {
        int e = idx * 2 + q;
        if (e < ETOT) {
            int src, dst;
            edge_sd(e, EI, src, dst);
            int pos = atomicAdd(&g_cursor[dst], 1);
            g_csr_src[pos] = src;
        }
    }
}

// Single-pass conv1 attention: 8 lanes per destination, all 8 heads fused.
// Also re-zeroes g_deg for the next replay.
__global__ __launch_bounds__(256) void conv1_attn_kernel() {
    __shared__ float sps[24], spd[24];
    if (threadIdx.x < 24) {
        sps[threadIdx.x] = g_psrc[threadIdx.x];
        spd[threadIdx.x] = g_pdst[threadIdx.x];
    }
    __syncthreads();
    int gid = blockIdx.x * blockDim.x + threadIdx.x;
    int d = gid >> 3;
    int sub = threadIdx.x & 7;
    if (sub == 0) g_deg[d] = 0;          // for next replay

    float ps0[8], ps1[8], ps2[8];
    #pragma unroll
    for (int h = 0; h < 8; h++) { ps0[h] = sps[h]; ps1[h] = sps[8 + h]; ps2[h] = sps[16 + h]; }

    float4 xd = g_xf[d];
    float ad[8];
    #pragma unroll
    for (int h = 0; h < 8; h++)
        ad[h] = fmaf(xd.x, spd[h], fmaf(xd.y, spd[8 + h], xd.z * spd[16 + h]));

    int start = g_rowptr[d];
    int deg = g_rowptr[d + 1] - start;

    float se[8], sx[8], sy[8], sz[8];
    #pragma unroll
    for (int h = 0; h < 8; h++) { se[h] = 0.f; sx[h] = 0.f; sy[h] = 0.f; sz[h] = 0.f; }

    for (int e = sub; e < deg; e += 8) {
        int s = g_csr_src[start + e];
        float4 x = g_xf[s];
        #pragma unroll
        for (int h = 0; h < 8; h++) {
            float a = fmaf(x.x, ps0[h], fmaf(x.y, ps1[h], x.z * ps2[h]));
            float ea = fexp(leaky(a + ad[h]));
            se[h] += ea;
            sx[h] = fmaf(ea, x.x, sx[h]);
            sy[h] = fmaf(ea, x.y, sy[h]);
            sz[h] = fmaf(ea, x.z, sz[h]);
        }
    }
    #pragma unroll
    for (int o = 4; o > 0; o >>= 1) {
        #pragma unroll
        for (int h = 0; h < 8; h++) {
            se[h] += __shfl_xor_sync(0xffffffffu, se[h], o);
            sx[h] += __shfl_xor_sync(0xffffffffu, sx[h], o);
            sy[h] += __shfl_xor_sync(0xffffffffu, sy[h], o);
            sz[h] += __shfl_xor_sync(0xffffffffu, sz[h], o);
        }
    }
    if (sub == 0) {
        #pragma unroll
        for (int h = 0; h < 8; h++) {
            float inv = 1.0f / se[h];
            g_s[d * 24 + h * 3 + 0] = sx[h] * inv;
            g_s[d * 24 + h * 3 + 1] = sy[h] * inv;
            g_s[d * 24 + h * 3 + 2] = sz[h] * inv;
        }
    }
}

// Fused expand + GEMM + attn2 epilogue. x1 tile built in smem (kk-major, dup float2).
__global__ __launch_bounds__(256) void fgemm_kernel(const float* __restrict__ W1,
                                                    const float* __restrict__ b1,
                                                    const float* __restrict__ W2,
                                                    const float* __restrict__ as2,
                                                    const float* __restrict__ ad2) {
    __shared__ float  sW1[3 * F1];       // 12 KB
    __shared__ float  sB1[F1];           // 4 KB
    __shared__ float  sS[64 * 24];       // 6 KB
    __shared__ float2 sAt[32][68];       // x1 tile transposed [kk][row], dup halves (17.4 KB)
    __shared__ float  sB[32][EMBn];      // W2 chunk (8 KB)

    int tid = threadIdx.x;
    int row0 = blockIdx.x * 64;

    for (int i = tid; i < 3 * F1; i += 256) sW1[i] = W1[i];
    for (int i = tid; i < F1; i += 256)     sB1[i] = b1[i];
    for (int i = tid; i < 64 * 24; i += 256) sS[i] = g_s[row0 * 24 + i];

    int tx = tid % 16, ty = tid / 16;
    int br = tid & 63;             // build row 0..63
    int bc0 = (tid >> 6) * 8;      // build kk base within chunk

    float2 acc[4][2];
    #pragma unroll
    for (int i = 0; i < 4; i++) { acc[i][0] = make_float2(0.f, 0.f); acc[i][1] = make_float2(0.f, 0.f); }

    for (int kc = 0; kc < F1; kc += 32) {
        __syncthreads();
        {
            int h = kc >> 7;
            float s0 = sS[br * 24 + h * 3 + 0];
            float s1 = sS[br * 24 + h * 3 + 1];
            float s2 = sS[br * 24 + h * 3 + 2];
            #pragma unroll
            for (int i = 0; i < 8; i++) {
                int col = kc + bc0 + i;
                float v = fmaf(s0, sW1[col], fmaf(s1, sW1[F1 + col], fmaf(s2, sW1[2 * F1 + col], sB1[col])));
                v = elu(v);
                sAt[bc0 + i][br] = make_float2(v, v);
            }
        }
        {
            int q0 = tid * 2;
            #pragma unroll
            for (int t = 0; t < 2; t++) {
                int q = q0 + t;
                int k = q >> 4, c4 = (q & 15) * 4;
                *(float4*)&sB[k][c4] = *(const float4*)&W2[(kc + k) * EMBn + c4];
            }
        }
        __syncthreads();
        #pragma unroll
        for (int kk = 0; kk < 32; kk++) {
            float4 b = *(const float4*)&sB[kk][tx * 4];
            float2 b01 = make_float2(b.x, b.y);
            float2 b23 = make_float2(b.z, b.w);
            float4 A01 = *(const float4*)&sAt[kk][ty * 4];       // rows 0,1 (dup pairs)
            float4 A23 = *(const float4*)&sAt[kk][ty * 4 + 2];   // rows 2,3
            float2 a0 = make_float2(A01.x, A01.y);
            float2 a1 = make_float2(A01.z, A01.w);
            float2 a2 = make_float2(A23.x, A23.y);
            float2 a3 = make_float2(A23.z, A23.w);
            acc[0][0] = ffma2(a0, b01, acc[0][0]); acc[0][1] = ffma2(a0, b23, acc[0][1]);
            acc[1][0] = ffma2(a1, b01, acc[1][0]); acc[1][1] = ffma2(a1, b23, acc[1][1]);
            acc[2][0] = ffma2(a2, b01, acc[2][0]); acc[2][1] = ffma2(a2, b23, acc[2][1]);
            acc[3][0] = ffma2(a3, b01, acc[3][0]); acc[3][1] = ffma2(a3, b23, acc[3][1]);
        }
    }
    // store h2
    #pragma unroll
    for (int i = 0; i < 4; i++) {
        int r = row0 + ty * 4 + i;
        g_h2[r * EMBn + tx * 4 + 0] = acc[i][0].x;
        g_h2[r * EMBn + tx * 4 + 1] = acc[i][0].y;
        g_h2[r * EMBn + tx * 4 + 2] = acc[i][1].x;
        g_h2[r * EMBn + tx * 4 + 3] = acc[i][1].y;
    }
    // attn2 epilogue
    float4 a_s = *(const float4*)&as2[tx * 4];
    float4 a_d = *(const float4*)&ad2[tx * 4];
    #pragma unroll
    for (int i = 0; i < 4; i++) {
        float ss = acc[i][0].x * a_s.x + acc[i][0].y * a_s.y + acc[i][1].x * a_s.z + acc[i][1].y * a_s.w;
        float sd = acc[i][0].x * a_d.x + acc[i][0].y * a_d.y + acc[i][1].x * a_d.z + acc[i][1].y * a_d.w;
        #pragma unroll
        for (int o = 1; o < 16; o <<= 1) {
            ss += __shfl_xor_sync(0xffffffffu, ss, o);
            sd += __shfl_xor_sync(0xffffffffu, sd, o);
        }
        if (tx == 0) {
            g_a2s[row0 + ty * 4 + i] = ss;
            g_a2d[row0 + ty * 4 + i] = sd;
        }
    }
}

// Single-pass per-dst softmax + aggregation of h2, fused elu(+b2) -> x2 TRANSPOSED
__global__ void conv2_agg_kernel(const float* __restrict__ b2) {
    __shared__ float wbuf[8][128];
    __shared__ int   ibuf[8][128];
    int wg = (blockIdx.x * blockDim.x + threadIdx.x) >> 5;
    if (wg >= NT) return;
    int lane = threadIdx.x & 31;
    int w = (threadIdx.x >> 5) & 7;
    int d = wg;
    int start = g_rowptr[d];
    int deg = g_rowptr[d + 1] - start;
    float adv = g_a2d[d];
    float se = 0.f;
    float2 acc = make_float2(0.f, 0.f);
    for (int base = 0; base < deg; base += 128) {
        int cnt = min(128, deg - base);
        for (int e = lane; e < cnt; e += 32) {
            int s = g_csr_src[start + base + e];
            float ea = fexp(leaky(g_a2s[s] + adv));
            wbuf[w][e] = ea;
            ibuf[w][e] = s;
            se += ea;
        }
        __syncwarp();
        #pragma unroll 4
        for (int e = 0; e < cnt; e++) {
            float ea = wbuf[w][e];
            int s = ibuf[w][e];
            float2 v = ((const float2*)(g_h2 + s * 64))[lane];
            acc.x = fmaf(ea, v.x, acc.x);
            acc.y = fmaf(ea, v.y, acc.y);
        }
        __syncwarp();
    }
    se = warp_sum(se);
    float inv = 1.0f / se;
    float2 bb = ((const float2*)b2)[lane];
    float r0 = elu(acc.x * inv + bb.x);
    float r1 = elu(acc.y * inv + bb.y);
    // transposed store: k = (n_local*64 + c), b innermost
    int b = d / Nn, n = d - b * Nn;
    int c = lane * 2;
    g_x2t[(n * 64 + c) * 16 + b]     = r0;
    g_x2t[(n * 64 + c + 1) * 16 + b] = r1;
}

// split-K stage 1 over transposed x2: smem-staged chunk, FFMA2 over b-pairs
__global__ __launch_bounds__(128) void mlp1_stage1(const float* __restrict__ mw1) {
    __shared__ __align__(16) float sx[CK * 16];     // 10 KB
    int c = blockIdx.x;
    int tid = threadIdx.x;
    int k0 = c * CK;
    const float4* gx4 = (const float4*)(g_x2t + k0 * 16);
    float4* sx4 = (float4*)sx;
    #pragma unroll
    for (int i = 0; i < 5; i++)
        sx4[tid + i * 128] = gx4[tid + i * 128];    // 640 float4
    __syncthreads();
    int j = tid;
    float2 acc[8];
    #pragma unroll
    for (int p = 0; p < 8; p++) acc[p] = make_float2(0.f, 0.f);
    #pragma unroll 2
    for (int k = 0; k < CK; k++) {
        float wv = mw1[(k0 + k) * HIDn + j];
        float2 w2 = make_float2(wv, wv);
        float4 x0 = sx4[k * 4 + 0];
        float4 x1 = sx4[k * 4 + 1];
        float4 x2 = sx4[k * 4 + 2];
        float4 x3 = sx4[k * 4 + 3];
        acc[0] = ffma2(make_float2(x0.x, x0.y), w2, acc[0]);
        acc[1] = ffma2(make_float2(x0.z, x0.w), w2, acc[1]);
        acc[2] = ffma2(make_float2(x1.x, x1.y), w2, acc[2]);
        acc[3] = ffma2(make_float2(x1.z, x1.w), w2, acc[3]);
        acc[4] = ffma2(make_float2(x2.x, x2.y), w2, acc[4]);
        acc[5] = ffma2(make_float2(x2.z, x2.w), w2, acc[5]);
        acc[6] = ffma2(make_float2(x3.x, x3.y), w2, acc[6]);
        acc[7] = ffma2(make_float2(x3.z, x3.w), w2, acc[7]);
    }
    #pragma unroll
    for (int p = 0; p < 8; p++) {
        g_part[(c * 16 + 2 * p) * HIDn + j]     = acc[p].x;
        g_part[(c * 16 + 2 * p + 1) * HIDn + j] = acc[p].y;
    }
}

__global__ void mlp1_reduce(const float* __restrict__ mb1) {
    int idx = blockIdx.x * blockDim.x + threadIdx.x;
    if (idx >= 16 * HIDn) return;
    int b = idx >> 7, j = idx & 127;
    float s = 0.f;
    #pragma unroll 4
    for (int c = 0; c < NCHUNK; c++)
        s += g_part[(c * 16 + b) * HIDn + j];
    s += mb1[j];
    g_y1[b * HIDn + j] = fmaxf(s, 0.f);
}

__global__ void mlp2_kernel(const float* __restrict__ mw2, const float* __restrict__ mb2) {
    __shared__ float ys[16 * HIDn];
    int tid = threadIdx.x;
    for (int i = tid; i < 16 * HIDn; i += 128) ys[i] = g_y1[i];
    __syncthreads();
    int j = tid;
    float acc[16];
    #pragma unroll
    for (int b = 0; b < 16; b++) acc[b] = 0.f;
    #pragma unroll 4
    for (int k = 0; k < HIDn; k++) {
        float wv = mw2[k * HIDn + j];
        #pragma unroll
        for (int b = 0; b < 16; b++)
            acc[b] = fmaf(ys[b * HIDn + k], wv, acc[b]);
    }
    #pragma unroll
    for (int b = 0; b < 16; b++)
        g_y2[b * HIDn + j] = fmaxf(acc[b] + mb2[j], 0.f);
}

__global__ void out_kernel(const float* __restrict__ ow, const float* __restrict__ ob,
                           float* __restrict__ out) {
    __shared__ float ys[16 * HIDn];
    int tid = threadIdx.x;
    for (int i = tid; i < 16 * HIDn; i += 128) ys[i] = g_y2[i];
    __syncthreads();
    int j = blockIdx.x * 64 + (tid & 63);
    int bh = tid >> 6;
    if (j >= Nn) return;
    float acc[8];
    #pragma unroll
    for (int b = 0; b < 8; b++) acc[b] = 0.f;
    const float* y = ys + bh * 8 * HIDn;
    #pragma unroll 4
    for (int k = 0; k < HIDn; k++) {
        float wv = ow[k * Nn + j];
        #pragma unroll
        for (int b = 0; b < 8; b++)
            acc[b] = fmaf(y[b * HIDn + k], wv, acc[b]);
    }
    float obj = ob[j];
    #pragma unroll
    for (int b = 0; b < 8; b++) {
        float v = acc[b] + obj;
        out[(bh * 8 + b) * Nn + j] = 1.0f / (1.0f + fexp(-v));
    }
}

// ------------------------- launch -------------------------
extern "C" void kernel_launch(void* const* d_in, const int* in_sizes, int n_in,
                              void* d_out, int out_size) {
    const float* actions = (const float*)d_in[0];
    const float* nodef   = (const float*)d_in[1];
    const int*   ei      = (const int*)d_in[2];
    const float* W1  = (const float*)d_in[3];
    const float* as1 = (const float*)d_in[4];
    const float* ad1 = (const float*)d_in[5];
    const float* b1  = (const float*)d_in[6];
    const float* W2  = (const float*)d_in[7];
    const float* as2 = (const float*)d_in[8];
    const float* ad2 = (const float*)d_in[9];
    const float* b2  = (const float*)d_in[10];
    const float* mw1 = (const float*)d_in[11];
    const float* mb1 = (const float*)d_in[12];
    const float* mw2 = (const float*)d_in[13];
    const float* mb2 = (const float*)d_in[14];
    const float* ow  = (const float*)d_in[15];
    const float* ob  = (const float*)d_in[16];
    float* out = (float*)d_out;

    nd_kernel<<<64 + 532, 256>>>(actions, nodef, W1, as1, ad1, ei);
    scan_kernel<<<1, 1024>>>();
    scatter_kernel<<<532, 256>>>(ei);
    conv1_attn_kernel<<<NT * 8 / 256, 256>>>();
    fgemm_kernel<<<NT / 64, 256>>>(W1, b1, W2, as2, ad2);
    conv2_agg_kernel<<<NT / 8, 256>>>(b2);
    mlp1_stage1<<<NCHUNK, 128>>>(mw1);
    mlp1_reduce<<<16, 128>>>(mb1);
    mlp2_kernel<<<1, 128>>>(mw2, mb2);
    out_kernel<<<16, 128>>>(ow, ob, out);
}

// round 7
// speedup vs baseline: 2.0102x; 1.1184x over previous
#include <cuda_runtime.h>
#include <math.h>

#define Bn 16
#define Nn 1000
#define En 16000
#define NT 16000          /* Bn*Nn total nodes  */
#define EBASE 256000      /* Bn*En edges before self loops */
#define ETOT 272000       /* + NT self loops */
#define TWOE 32000
#define HALFB 8

#define H1n 8
#define F1 1024           /* H1*C1 */
#define EMBn 64
#define HIDn 128
#define BCAP 96           /* bucket capacity per dst */

#define NCHUNK 400
#define CK 160            /* 400*160 = 64000 */

// ------------------------- scratch (static, no allocs) -------------------------
__device__ __align__(16) float4 g_xf[NT];           // node features (x,y,nf,0)
__device__ float g_psrc[24];                         // [3][8]
__device__ float g_pdst[24];
__device__ int   g_cursor[NT];                       // zero at load; re-zeroed by mlp1_stage1
__device__ int   g_bucket[NT * BCAP];                // CSR-free edge buckets
__device__ float g_s[NT * 24];                       // [NT][8][3]
__device__ __align__(16) float g_h2[NT * EMBn];
__device__ float g_a2s[NT];
__device__ float g_a2d[NT];
__device__ __align__(16) float g_x2t[64000 * 16];    // transposed: [k=(n*64+c)][b]
__device__ float g_part[NCHUNK * 16 * HIDn];         // 3.3 MB
__device__ float g_y1[16 * HIDn];
__device__ float g_y2[16 * HIDn];

// ------------------------- helpers -------------------------
__device__ __forceinline__ void edge_sd(int e, const int* __restrict__ EI, int& src, int& dst) {
    if (e < EBASE) {
        int b   = e / TWOE;          // graph providing src (0..7)
        int rem = e - b * TWOE;      // r*E + j
        src = EI[b * TWOE + rem] + b * Nn;
        int b2 = b + HALFB;          // graph providing dst (8..15)
        dst = EI[b2 * TWOE + rem] + b2 * Nn;
    } else {
        src = dst = e - EBASE;       // self loop
    }
}

__device__ __forceinline__ float warp_sum(float v) {
    #pragma unroll
    for (int o = 16; o > 0; o >>= 1) v += __shfl_xor_sync(0xffffffffu, v, o);
    return v;
}
__device__ __forceinline__ float leaky(float v) { return v > 0.f ? v : 0.2f * v; }
__device__ __forceinline__ float elu(float v)   { return v > 0.f ? v : (__expf(v) - 1.0f); }

// packed fp32x2 FMA (sm_100+)
__device__ __forceinline__ float2 ffma2(float2 a, float2 b, float2 c) {
    unsigned long long A = *reinterpret_cast<unsigned long long*>(&a);
    unsigned long long B = *reinterpret_cast<unsigned long long*>(&b);
    unsigned long long C = *reinterpret_cast<unsigned long long*>(&c);
    unsigned long long D;
    asm("fma.rn.f32x2 %0, %1, %2, %3;" : "=l"(D) : "l"(A), "l"(B), "l"(C));
    return *reinterpret_cast<float2*>(&D);
}

// ------------------------- kernels -------------------------

// Fused builder: node features (blocks 0-62) + projections (block 63) + bucket scatter (64+)
__global__ void build_kernel(const float* __restrict__ actions,
                             const float* __restrict__ nodef,
                             const float* __restrict__ W1,
                             const float* __restrict__ as1,
                             const float* __restrict__ ad1,
                             const int* __restrict__ EI) {
    int blk = blockIdx.x;
    if (blk < 63) {
        int n = blk * 256 + threadIdx.x;
        if (n >= NT) return;
        float ax = actions[n * 2 + 0];
        float ay = actions[n * 2 + 1];
        float nf = nodef[n];
        g_xf[n] = make_float4(ax, ay, nf, 0.f);
    } else if (blk == 63) {
        int t = threadIdx.x;
        if (t < 48) {
            int which = t / 24;
            int r = t % 24;
            int k = r / 8, h = r % 8;
            const float* att = which ? ad1 : as1;
            float s = 0.f;
            for (int c = 0; c < 128; c++)
                s += W1[k * F1 + h * 128 + c] * att[h * 128 + c];
            (which ? g_pdst : g_psrc)[k * 8 + h] = s;
        }
    } else {
        int idx = (blk - 64) * 256 + threadIdx.x;
        #pragma unroll
        for (int q = 0; q < 4; q++) {
            int e = idx * 4 + q;
            if (e < ETOT) {
                int src, dst;
                edge_sd(e, EI, src, dst);
                int pos = atomicAdd(&g_cursor[dst], 1);
                g_bucket[dst * BCAP + pos] = src;
            }
        }
    }
}

// conv1 attention: ONE thread per (dst, head). No shuffles. deg==1 fast path.
__global__ __launch_bounds__(256) void conv1_attn_kernel() {
    int gid = blockIdx.x * blockDim.x + threadIdx.x;
    int d = gid >> 3;
    int h = gid & 7;
    float4 xd = g_xf[d];
    int deg = g_cursor[d];
    float* sp = g_s + d * 24 + h * 3;
    if (deg == 1) {
        // only the self loop: softmax weight = 1 -> s = x[d]
        sp[0] = xd.x; sp[1] = xd.y; sp[2] = xd.z;
        return;
    }
    float p0 = g_psrc[h], p1 = g_psrc[8 + h], p2 = g_psrc[16 + h];
    float q0 = g_pdst[h], q1 = g_pdst[8 + h], q2 = g_pdst[16 + h];
    float adv = fmaf(xd.x, q0, fmaf(xd.y, q1, xd.z * q2));
    const int* bkt = g_bucket + d * BCAP;
    float se = 0.f, sx = 0.f, sy = 0.f, sz = 0.f;
    for (int i = 0; i < deg; i++) {
        int s = bkt[i];
        float4 x = g_xf[s];
        float a = fmaf(x.x, p0, fmaf(x.y, p1, x.z * p2)) + adv;
        float ea = __expf(leaky(a));
        se += ea;
        sx = fmaf(ea, x.x, sx);
        sy = fmaf(ea, x.y, sy);
        sz = fmaf(ea, x.z, sz);
    }
    float inv = 1.0f / se;
    sp[0] = sx * inv; sp[1] = sy * inv; sp[2] = sz * inv;
}

// Fused expand + GEMM + attn2 epilogue, double-buffered smem.
__global__ __launch_bounds__(256) void fgemm_kernel(const float* __restrict__ W1,
                                                    const float* __restrict__ b1,
                                                    const float* __restrict__ W2,
                                                    const float* __restrict__ as2,
                                                    const float* __restrict__ ad2) {
    __shared__ float  sW1[3 * F1];          // 12 KB
    __shared__ float  sB1[F1];              // 4 KB
    __shared__ float  sS[64 * 24];          // 6 KB
    __shared__ float2 sAt[2][32][68];       // x1 tile transposed, dup pairs (34.8 KB)
    __shared__ float  sB[2][32][EMBn];      // W2 chunks (16 KB)

    int tid = threadIdx.x;
    int row0 = blockIdx.x * 64;

    for (int i = tid; i < 3 * F1; i += 256) sW1[i] = W1[i];
    for (int i = tid; i < F1; i += 256)     sB1[i] = b1[i];
    for (int i = tid; i < 64 * 24; i += 256) sS[i] = g_s[row0 * 24 + i];
    __syncthreads();

    int tx = tid % 16, ty = tid / 16;
    int br = tid & 63;             // build row 0..63
    int bc0 = (tid >> 6) * 8;      // build kk base within chunk

    float2 acc[4][2];
    #pragma unroll
    for (int i = 0; i < 4; i++) { acc[i][0] = make_float2(0.f, 0.f); acc[i][1] = make_float2(0.f, 0.f); }

    // ---- build chunk helper (inlined twice) ----
    #define BUILD_CHUNK(cidx, buf)                                                        \
    {                                                                                     \
        int kc_ = (cidx) * 32;                                                            \
        int h_ = kc_ >> 7;                                                                \
        float s0 = sS[br * 24 + h_ * 3 + 0];                                              \
        float s1 = sS[br * 24 + h_ * 3 + 1];                                              \
        float s2 = sS[br * 24 + h_ * 3 + 2];                                              \
        int cb = kc_ + bc0;                                                               \
        float4 w0a = *(const float4*)&sW1[cb];                                            \
        float4 w0b = *(const float4*)&sW1[cb + 4];                                        \
        float4 w1a = *(const float4*)&sW1[F1 + cb];                                       \
        float4 w1b = *(const float4*)&sW1[F1 + cb + 4];                                   \
        float4 w2a = *(const float4*)&sW1[2 * F1 + cb];                                   \
        float4 w2b = *(const float4*)&sW1[2 * F1 + cb + 4];                               \
        float4 ba  = *(const float4*)&sB1[cb];                                            \
        float4 bbv = *(const float4*)&sB1[cb + 4];                                        \
        float v0 = elu(fmaf(s0, w0a.x, fmaf(s1, w1a.x, fmaf(s2, w2a.x, ba.x))));          \
        float v1 = elu(fmaf(s0, w0a.y, fmaf(s1, w1a.y, fmaf(s2, w2a.y, ba.y))));          \
        float v2 = elu(fmaf(s0, w0a.z, fmaf(s1, w1a.z, fmaf(s2, w2a.z, ba.z))));          \
        float v3 = elu(fmaf(s0, w0a.w, fmaf(s1, w1a.w, fmaf(s2, w2a.w, ba.w))));          \
        float v4 = elu(fmaf(s0, w0b.x, fmaf(s1, w1b.x, fmaf(s2, w2b.x, bbv.x))));         \
        float v5 = elu(fmaf(s0, w0b.y, fmaf(s1, w1b.y, fmaf(s2, w2b.y, bbv.y))));         \
        float v6 = elu(fmaf(s0, w0b.z, fmaf(s1, w1b.z, fmaf(s2, w2b.z, bbv.z))));         \
        float v7 = elu(fmaf(s0, w0b.w, fmaf(s1, w1b.w, fmaf(s2, w2b.w, bbv.w))));         \
        sAt[buf][bc0 + 0][br] = make_float2(v0, v0);                                      \
        sAt[buf][bc0 + 1][br] = make_float2(v1, v1);                                      \
        sAt[buf][bc0 + 2][br] = make_float2(v2, v2);                                      \
        sAt[buf][bc0 + 3][br] = make_float2(v3, v3);                                      \
        sAt[buf][bc0 + 4][br] = make_float2(v4, v4);                                      \
        sAt[buf][bc0 + 5][br] = make_float2(v5, v5);                                      \
        sAt[buf][bc0 + 6][br] = make_float2(v6, v6);                                      \
        sAt[buf][bc0 + 7][br] = make_float2(v7, v7);                                      \
        int q0 = tid * 2;                                                                 \
        int k0_ = q0 >> 4, c40 = (q0 & 15) * 4;                                           \
        *(float4*)&sB[buf][k0_][c40] = *(const float4*)&W2[(kc_ + k0_) * EMBn + c40];     \
        int q1 = q0 + 1;                                                                  \
        int k1_ = q1 >> 4, c41 = (q1 & 15) * 4;                                           \
        *(float4*)&sB[buf][k1_][c41] = *(const float4*)&W2[(kc_ + k1_) * EMBn + c41];     \
    }

    BUILD_CHUNK(0, 0)
    __syncthreads();

    for (int c = 0; c < 32; c++) {
        int cur = c & 1;
        if (c + 1 < 32) BUILD_CHUNK(c + 1, (c + 1) & 1)
        #pragma unroll
        for (int kk = 0; kk < 32; kk++) {
            float4 b = *(const float4*)&sB[cur][kk][tx * 4];
            float2 b01 = make_float2(b.x, b.y);
            float2 b23 = make_float2(b.z, b.w);
            float4 A01 = *(const float4*)&sAt[cur][kk][ty * 4];
            float4 A23 = *(const float4*)&sAt[cur][kk][ty * 4 + 2];
            float2 a0 = make_float2(A01.x, A01.y);
            float2 a1 = make_float2(A01.z, A01.w);
            float2 a2 = make_float2(A23.x, A23.y);
            float2 a3 = make_float2(A23.z, A23.w);
            acc[0][0] = ffma2(a0, b01, acc[0][0]); acc[0][1] = ffma2(a0, b23, acc[0][1]);
            acc[1][0] = ffma2(a1, b01, acc[1][0]); acc[1][1] = ffma2(a1, b23, acc[1][1]);
            acc[2][0] = ffma2(a2, b01, acc[2][0]); acc[2][1] = ffma2(a2, b23, acc[2][1]);
            acc[3][0] = ffma2(a3, b01, acc[3][0]); acc[3][1] = ffma2(a3, b23, acc[3][1]);
        }
        __syncthreads();
    }

    // store h2
    #pragma unroll
    for (int i = 0; i < 4; i++) {
        int r = row0 + ty * 4 + i;
        g_h2[r * EMBn + tx * 4 + 0] = acc[i][0].x;
        g_h2[r * EMBn + tx * 4 + 1] = acc[i][0].y;
        g_h2[r * EMBn + tx * 4 + 2] = acc[i][1].x;
        g_h2[r * EMBn + tx * 4 + 3] = acc[i][1].y;
    }
    // attn2 epilogue
    float4 a_s = *(const float4*)&as2[tx * 4];
    float4 a_d = *(const float4*)&ad2[tx * 4];
    #pragma unroll
    for (int i = 0; i < 4; i++) {
        float ss = acc[i][0].x * a_s.x + acc[i][0].y * a_s.y + acc[i][1].x * a_s.z + acc[i][1].y * a_s.w;
        float sd = acc[i][0].x * a_d.x + acc[i][0].y * a_d.y + acc[i][1].x * a_d.z + acc[i][1].y * a_d.w;
        #pragma unroll
        for (int o = 1; o < 16; o <<= 1) {
            ss += __shfl_xor_sync(0xffffffffu, ss, o);
            sd += __shfl_xor_sync(0xffffffffu, sd, o);
        }
        if (tx == 0) {
            g_a2s[row0 + ty * 4 + i] = ss;
            g_a2d[row0 + ty * 4 + i] = sd;
        }
    }
}

// conv2: warp per dst, single-pass softmax-agg, deg==1 fast path, transposed store
__global__ void conv2_agg_kernel(const float* __restrict__ b2) {
    __shared__ float wbuf[8][BCAP];
    __shared__ int   ibuf[8][BCAP];
    int wg = (blockIdx.x * blockDim.x + threadIdx.x) >> 5;
    if (wg >= NT) return;
    int lane = threadIdx.x & 31;
    int w = (threadIdx.x >> 5) & 7;
    int d = wg;
    int deg = g_cursor[d];
    int b = d / Nn, n = d - b * Nn;
    int c = lane * 2;
    float2 bb = ((const float2*)b2)[lane];
    if (deg == 1) {
        float2 v = ((const float2*)(g_h2 + d * 64))[lane];
        g_x2t[(n * 64 + c) * 16 + b]     = elu(v.x + bb.x);
        g_x2t[(n * 64 + c + 1) * 16 + b] = elu(v.y + bb.y);
        return;
    }
    const int* bkt = g_bucket + d * BCAP;
    float adv = g_a2d[d];
    float se = 0.f;
    for (int e = lane; e < deg; e += 32) {
        int s = bkt[e];
        float ea = __expf(leaky(g_a2s[s] + adv));
        wbuf[w][e] = ea;
        ibuf[w][e] = s;
        se += ea;
    }
    __syncwarp();
    float2 acc = make_float2(0.f, 0.f);
    #pragma unroll 4
    for (int e = 0; e < deg; e++) {
        float ea = wbuf[w][e];
        int s = ibuf[w][e];
        float2 v = ((const float2*)(g_h2 + s * 64))[lane];
        acc.x = fmaf(ea, v.x, acc.x);
        acc.y = fmaf(ea, v.y, acc.y);
    }
    se = warp_sum(se);
    float inv = 1.0f / se;
    g_x2t[(n * 64 + c) * 16 + b]     = elu(acc.x * inv + bb.x);
    g_x2t[(n * 64 + c + 1) * 16 + b] = elu(acc.y * inv + bb.y);
}

// split-K stage 1 over transposed x2 + cursor re-zero for next replay
__global__ __launch_bounds__(128) void mlp1_stage1(const float* __restrict__ mw1) {
    __shared__ __align__(16) float sx[CK * 16];     // 10 KB
    int cblk = blockIdx.x;
    int tid = threadIdx.x;
    int zid = cblk * 128 + tid;
    if (zid < NT) g_cursor[zid] = 0;                // reset buckets for next launch
    int k0 = cblk * CK;
    const float4* gx4 = (const float4*)(g_x2t + k0 * 16);
    float4* sx4 = (float4*)sx;
    #pragma unroll
    for (int i = 0; i < 5; i++)
        sx4[tid + i * 128] = gx4[tid + i * 128];    // 640 float4
    __syncthreads();
    int j = tid;
    float2 acc[8];
    #pragma unroll
    for (int p = 0; p < 8; p++) acc[p] = make_float2(0.f, 0.f);
    #pragma unroll 2
    for (int k = 0; k < CK; k++) {
        float wv = mw1[(k0 + k) * HIDn + j];
        float2 w2 = make_float2(wv, wv);
        float4 x0 = sx4[k * 4 + 0];
        float4 x1 = sx4[k * 4 + 1];
        float4 x2 = sx4[k * 4 + 2];
        float4 x3 = sx4[k * 4 + 3];
        acc[0] = ffma2(make_float2(x0.x, x0.y), w2, acc[0]);
        acc[1] = ffma2(make_float2(x0.z, x0.w), w2, acc[1]);
        acc[2] = ffma2(make_float2(x1.x, x1.y), w2, acc[2]);
        acc[3] = ffma2(make_float2(x1.z, x1.w), w2, acc[3]);
        acc[4] = ffma2(make_float2(x2.x, x2.y), w2, acc[4]);
        acc[5] = ffma2(make_float2(x2.z, x2.w), w2, acc[5]);
        acc[6] = ffma2(make_float2(x3.x, x3.y), w2, acc[6]);
        acc[7] = ffma2(make_float2(x3.z, x3.w), w2, acc[7]);
    }
    #pragma unroll
    for (int p = 0; p < 8; p++) {
        g_part[(cblk * 16 + 2 * p) * HIDn + j]     = acc[p].x;
        g_part[(cblk * 16 + 2 * p + 1) * HIDn + j] = acc[p].y;
    }
}

__global__ void mlp1_reduce(const float* __restrict__ mb1) {
    int idx = blockIdx.x * blockDim.x + threadIdx.x;
    if (idx >= 16 * HIDn) return;
    int b = idx >> 7, j = idx & 127;
    float s = 0.f;
    #pragma unroll 4
    for (int c = 0; c < NCHUNK; c++)
        s += g_part[(c * 16 + b) * HIDn + j];
    s += mb1[j];
    g_y1[b * HIDn + j] = fmaxf(s, 0.f);
}

__global__ void mlp2_kernel(const float* __restrict__ mw2, const float* __restrict__ mb2) {
    __shared__ float ys[16 * HIDn];
    int tid = threadIdx.x;
    for (int i = tid; i < 16 * HIDn; i += 128) ys[i] = g_y1[i];
    __syncthreads();
    int j = tid;
    float acc[16];
    #pragma unroll
    for (int b = 0; b < 16; b++) acc[b] = 0.f;
    #pragma unroll 4
    for (int k = 0; k < HIDn; k++) {
        float wv = mw2[k * HIDn + j];
        #pragma unroll
        for (int b = 0; b < 16; b++)
            acc[b] = fmaf(ys[b * HIDn + k], wv, acc[b]);
    }
    #pragma unroll
    for (int b = 0; b < 16; b++)
        g_y2[b * HIDn + j] = fmaxf(acc[b] + mb2[j], 0.f);
}

__global__ void out_kernel(const float* __restrict__ ow, const float* __restrict__ ob,
                           float* __restrict__ out) {
    __shared__ float ys[16 * HIDn];
    int tid = threadIdx.x;
    for (int i = tid; i < 16 * HIDn; i += 128) ys[i] = g_y2[i];
    __syncthreads();
    int j = blockIdx.x * 64 + (tid & 63);
    int bh = tid >> 6;
    if (j >= Nn) return;
    float acc[8];
    #pragma unroll
    for (int b = 0; b < 8; b++) acc[b] = 0.f;
    const float* y = ys + bh * 8 * HIDn;
    #pragma unroll 4
    for (int k = 0; k < HIDn; k++) {
        float wv = ow[k * Nn + j];
        #pragma unroll
        for (int b = 0; b < 8; b++)
            acc[b] = fmaf(y[b * HIDn + k], wv, acc[b]);
    }
    float obj = ob[j];
    #pragma unroll
    for (int b = 0; b < 8; b++) {
        float v = acc[b] + obj;
        out[(bh * 8 + b) * Nn + j] = 1.0f / (1.0f + __expf(-v));
    }
}

// ------------------------- launch -------------------------
extern "C" void kernel_launch(void* const* d_in, const int* in_sizes, int n_in,
                              void* d_out, int out_size) {
    const float* actions = (const float*)d_in[0];
    const float* nodef   = (const float*)d_in[1];
    const int*   ei      = (const int*)d_in[2];
    const float* W1  = (const float*)d_in[3];
    const float* as1 = (const float*)d_in[4];
    const float* ad1 = (const float*)d_in[5];
    const float* b1  = (const float*)d_in[6];
    const float* W2  = (const float*)d_in[7];
    const float* as2 = (const float*)d_in[8];
    const float* ad2 = (const float*)d_in[9];
    const float* b2  = (const float*)d_in[10];
    const float* mw1 = (const float*)d_in[11];
    const float* mb1 = (const float*)d_in[12];
    const float* mw2 = (const float*)d_in[13];
    const float* mb2 = (const float*)d_in[14];
    const float* ow  = (const float*)d_in[15];
    const float* ob  = (const float*)d_in[16];
    float* out = (float*)d_out;

    build_kernel<<<64 + 266, 256>>>(actions, nodef, W1, as1, ad1, ei);
    conv1_attn_kernel<<<NT * 8 / 256, 256>>>();
    fgemm_kernel<<<NT / 64, 256>>>(W1, b1, W2, as2, ad2);
    conv2_agg_kernel<<<NT / 8, 256>>>(b2);
    mlp1_stage1<<<NCHUNK, 128>>>(mw1);
    mlp1_reduce<<<16, 128>>>(mb1);
    mlp2_kernel<<<1, 128>>>(mw2, mb2);
    out_kernel<<<16, 128>>>(ow, ob, out);
}